// round 2
// baseline (speedup 1.0000x reference)
#include <cuda_runtime.h>
#include <math.h>

// ---------------------------------------------------------------------------
// RWKV block: LN1 -> mix -> {k,v,r} GEMMs -> WKV scan -> Wo GEMM (+residual)
//            -> LN2 -> mix -> FFN (Wk_f relu^2, Wr_f sigmoid, Wv_f) -> out
// All fp32. GEMMs are TN (out[m,n] = sum_k act[m,k] * W[n,k]).
// ---------------------------------------------------------------------------

constexpr int B_ = 4, T_ = 4096, C_ = 2048, A_ = 2048, FF_ = 8192;
constexpr long BTC = (long)B_ * T_ * C_;     // 33,554,432
constexpr long BTA = (long)B_ * T_ * A_;     // 33,554,432
constexpr long BTF = (long)B_ * T_ * FF_;    // 134,217,728

// Scratch (device globals; allocation-free per harness rules)
__device__ float g_xn [BTC];
__device__ float g_mix[BTC];
__device__ float g_k  [BTA];
__device__ float g_v  [BTA];
__device__ float g_sr [BTA];
__device__ float g_y  [BTA];
__device__ float g_x1 [BTC];
__device__ float g_xn2[BTC];
__device__ float g_r  [BTC];
__device__ float g_kv [BTC];
__device__ float g_kf [BTF];

// ---------------------------------------------------------------------------
// LayerNorm: one block (256 threads) per row of C_=2048.
// Optionally writes last-timestep row to shift_out (new_tm_shift / new_cm_shift).
// ---------------------------------------------------------------------------
__global__ __launch_bounds__(256)
void ln_kernel(const float* __restrict__ x, const float* __restrict__ g,
               const float* __restrict__ b, float* __restrict__ out,
               float* __restrict__ shift_out)
{
    const int row = blockIdx.x;                      // b*T + t
    const float4* xr = (const float4*)(x + (size_t)row * C_);
    const int tid = threadIdx.x;

    float4 v0 = xr[tid];
    float4 v1 = xr[tid + 256];

    float s  = v0.x + v0.y + v0.z + v0.w + v1.x + v1.y + v1.z + v1.w;
    float sq = v0.x*v0.x + v0.y*v0.y + v0.z*v0.z + v0.w*v0.w
             + v1.x*v1.x + v1.y*v1.y + v1.z*v1.z + v1.w*v1.w;

    #pragma unroll
    for (int o = 16; o > 0; o >>= 1) {
        s  += __shfl_xor_sync(0xFFFFFFFFu, s,  o);
        sq += __shfl_xor_sync(0xFFFFFFFFu, sq, o);
    }
    __shared__ float ss[8], sqs[8];
    if ((tid & 31) == 0) { ss[tid >> 5] = s; sqs[tid >> 5] = sq; }
    __syncthreads();
    float ts = 0.f, tsq = 0.f;
    #pragma unroll
    for (int i = 0; i < 8; i++) { ts += ss[i]; tsq += sqs[i]; }

    const float mean = ts * (1.0f / C_);
    const float var  = tsq * (1.0f / C_) - mean * mean;
    const float rstd = rsqrtf(var + 1e-5f);

    const float4* g4 = (const float4*)g;
    const float4* b4 = (const float4*)b;
    float4 gg0 = g4[tid],       bb0 = b4[tid];
    float4 gg1 = g4[tid + 256], bb1 = b4[tid + 256];

    float4 o0, o1;
    o0.x = (v0.x - mean) * rstd * gg0.x + bb0.x;
    o0.y = (v0.y - mean) * rstd * gg0.y + bb0.y;
    o0.z = (v0.z - mean) * rstd * gg0.z + bb0.z;
    o0.w = (v0.w - mean) * rstd * gg0.w + bb0.w;
    o1.x = (v1.x - mean) * rstd * gg1.x + bb1.x;
    o1.y = (v1.y - mean) * rstd * gg1.y + bb1.y;
    o1.z = (v1.z - mean) * rstd * gg1.z + bb1.z;
    o1.w = (v1.w - mean) * rstd * gg1.w + bb1.w;

    float4* orow = (float4*)(out + (size_t)row * C_);
    orow[tid]       = o0;
    orow[tid + 256] = o1;

    if (shift_out != nullptr && (row % T_) == (T_ - 1)) {
        float4* sp = (float4*)(shift_out + (size_t)(row / T_) * C_);
        sp[tid]       = o0;
        sp[tid + 256] = o1;
    }
}

// ---------------------------------------------------------------------------
// Time-mix: out[b,t,c] = xn[b,t,c]*mix[c] + xx*(1-mix[c]),
// xx = shift[b,c] at t==0 else xn[b,t-1,c].
// Grid covers BTC/4 float4s exactly.
// ---------------------------------------------------------------------------
__global__ __launch_bounds__(256)
void mix_kernel(const float* __restrict__ xn, const float* __restrict__ shift,
                const float* __restrict__ mix, float* __restrict__ out)
{
    const long i4 = (long)blockIdx.x * 256 + threadIdx.x;  // float4 index
    const long e  = i4 * 4;
    const int  c4 = (int)((e % C_) >> 2);
    const long row = e / C_;
    const int  t  = (int)(row % T_);
    const int  bb = (int)(row / T_);

    float4 cur = ((const float4*)xn)[i4];
    float4 m   = ((const float4*)mix)[c4];
    float4 prev = (t == 0) ? ((const float4*)shift)[(long)bb * (C_ / 4) + c4]
                           : ((const float4*)xn)[i4 - C_ / 4];
    float4 o;
    o.x = cur.x * m.x + prev.x * (1.f - m.x);
    o.y = cur.y * m.y + prev.y * (1.f - m.y);
    o.z = cur.z * m.z + prev.z * (1.f - m.z);
    o.w = cur.w * m.w + prev.w * (1.f - m.w);
    ((float4*)out)[i4] = o;
}

// out[i] = a[i] * b[i]
__global__ __launch_bounds__(256)
void mul_kernel(const float* __restrict__ a, const float* __restrict__ b,
                float* __restrict__ out)
{
    const long i4 = (long)blockIdx.x * 256 + threadIdx.x;
    float4 x = ((const float4*)a)[i4];
    float4 y = ((const float4*)b)[i4];
    float4 o; o.x = x.x*y.x; o.y = x.y*y.y; o.z = x.z*y.z; o.w = x.w*y.w;
    ((float4*)out)[i4] = o;
}

// out[i] = base[i] + r[i] * kv[i]
__global__ __launch_bounds__(256)
void final_kernel(const float* __restrict__ base, const float* __restrict__ r,
                  const float* __restrict__ kv, float* __restrict__ out)
{
    const long i4 = (long)blockIdx.x * 256 + threadIdx.x;
    float4 xb = ((const float4*)base)[i4];
    float4 xr = ((const float4*)r)[i4];
    float4 xk = ((const float4*)kv)[i4];
    float4 o;
    o.x = xb.x + xr.x * xk.x;
    o.y = xb.y + xr.y * xk.y;
    o.z = xb.z + xr.z * xk.z;
    o.w = xb.w + xr.w * xk.w;
    ((float4*)out)[i4] = o;
}

// ---------------------------------------------------------------------------
// WKV scan: one thread per (b, a) channel, serial over T.
// ---------------------------------------------------------------------------
__global__ __launch_bounds__(256)
void wkv_kernel(const float* __restrict__ td, const float* __restrict__ tf,
                const float* __restrict__ k, const float* __restrict__ v,
                const float* __restrict__ state_in, float* __restrict__ y,
                float* __restrict__ state_out)
{
    const int gid = blockIdx.x * 256 + threadIdx.x;
    if (gid >= B_ * A_) return;
    const int b = gid / A_;
    const int a = gid % A_;

    const float w = -__expf(td[a]);
    const float u = tf[a];

    const size_t base = (size_t)b * T_ * A_ + a;
    const float* kp = k + base;
    const float* vp = v + base;
    float*       yp = y + base;

    const size_t si = ((size_t)b * A_ + a) * 3;
    float aa = state_in[si + 0];
    float bb = state_in[si + 1];
    float pp = state_in[si + 2];

    for (int t = 0; t < T_; t++) {
        const size_t off = (size_t)t * A_;
        const float kt = kp[off];
        const float vt = vp[off];

        float ww = u + kt;
        float p  = fmaxf(pp, ww);
        float e1 = __expf(pp - p);
        float e2 = __expf(ww - p);
        yp[off] = (e1 * aa + e2 * vt) / (e1 * bb + e2);

        ww = pp + w;
        p  = fmaxf(ww, kt);
        e1 = __expf(ww - p);
        e2 = __expf(kt - p);
        aa = e1 * aa + e2 * vt;
        bb = e1 * bb + e2;
        pp = p;
    }
    state_out[si + 0] = aa;
    state_out[si + 1] = bb;
    state_out[si + 2] = pp;
}

// ---------------------------------------------------------------------------
// SGEMM (TN): C[m,n] = sum_k A[m,k] * W[n,k]
// 128x128 block tile, BK=8, 8x8 microtile, 256 threads, float4 loads.
// EPI: 0 = none, 1 = sigmoid, 2 = relu^2, 3 = +residual
// M,N,K all divisible by tile dims for this problem (no bounds checks).
// ---------------------------------------------------------------------------
template <int EPI>
__global__ __launch_bounds__(256)
void sgemm_kernel(int M, int N, int K,
                  const float* __restrict__ A, const float* __restrict__ W,
                  const float* __restrict__ Res, float* __restrict__ C)
{
    constexpr int BM = 128, BN = 128, BK = 8, TM = 8, TN = 8;
    __shared__ float As[BK][BM];
    __shared__ float Bs[BK][BN];

    const int tid  = threadIdx.x;
    const int tRow = tid / 16;          // 0..15
    const int tCol = tid % 16;          // 0..15
    const int lRow = tid >> 1;          // 0..127
    const int lCol = (tid & 1) << 2;    // 0 or 4

    const float* Ab = A + (size_t)blockIdx.y * BM * K;
    const float* Wb = W + (size_t)blockIdx.x * BN * K;

    float acc[TM][TN];
    #pragma unroll
    for (int i = 0; i < TM; i++)
        #pragma unroll
        for (int j = 0; j < TN; j++) acc[i][j] = 0.f;

    float regM[TM], regN[TN];

    for (int k0 = 0; k0 < K; k0 += BK) {
        float4 a4 = *(const float4*)(Ab + (size_t)lRow * K + k0 + lCol);
        float4 b4 = *(const float4*)(Wb + (size_t)lRow * K + k0 + lCol);
        As[lCol + 0][lRow] = a4.x; As[lCol + 1][lRow] = a4.y;
        As[lCol + 2][lRow] = a4.z; As[lCol + 3][lRow] = a4.w;
        Bs[lCol + 0][lRow] = b4.x; Bs[lCol + 1][lRow] = b4.y;
        Bs[lCol + 2][lRow] = b4.z; Bs[lCol + 3][lRow] = b4.w;
        __syncthreads();

        #pragma unroll
        for (int kk = 0; kk < BK; kk++) {
            #pragma unroll
            for (int i = 0; i < TM; i++) regM[i] = As[kk][tRow * TM + i];
            #pragma unroll
            for (int j = 0; j < TN; j++) regN[j] = Bs[kk][tCol * TN + j];
            #pragma unroll
            for (int i = 0; i < TM; i++)
                #pragma unroll
                for (int j = 0; j < TN; j++)
                    acc[i][j] = fmaf(regM[i], regN[j], acc[i][j]);
        }
        __syncthreads();
    }

    #pragma unroll
    for (int i = 0; i < TM; i++) {
        const size_t m = (size_t)blockIdx.y * BM + tRow * TM + i;
        const size_t base = m * N + (size_t)blockIdx.x * BN + tCol * TN;
        #pragma unroll
        for (int j = 0; j < TN; j += 4) {
            float4 v;
            v.x = acc[i][j + 0]; v.y = acc[i][j + 1];
            v.z = acc[i][j + 2]; v.w = acc[i][j + 3];
            if (EPI == 1) {
                v.x = 1.f / (1.f + __expf(-v.x));
                v.y = 1.f / (1.f + __expf(-v.y));
                v.z = 1.f / (1.f + __expf(-v.z));
                v.w = 1.f / (1.f + __expf(-v.w));
            } else if (EPI == 2) {
                v.x = fmaxf(v.x, 0.f); v.x *= v.x;
                v.y = fmaxf(v.y, 0.f); v.y *= v.y;
                v.z = fmaxf(v.z, 0.f); v.z *= v.z;
                v.w = fmaxf(v.w, 0.f); v.w *= v.w;
            } else if (EPI == 3) {
                float4 r = *(const float4*)(Res + base + j);
                v.x += r.x; v.y += r.y; v.z += r.z; v.w += r.w;
            }
            *(float4*)(C + base + j) = v;
        }
    }
}

// ---------------------------------------------------------------------------
// Host launcher
// ---------------------------------------------------------------------------
extern "C" void kernel_launch(void* const* d_in, const int* in_sizes, int n_in,
                              void* d_out, int out_size)
{
    const float* x         = (const float*)d_in[0];
    const float* tm_shift  = (const float*)d_in[1];
    const float* wkv_state = (const float*)d_in[2];
    const float* cm_shift  = (const float*)d_in[3];
    const float* ln1_g     = (const float*)d_in[4];
    const float* ln1_b     = (const float*)d_in[5];
    const float* ln2_g     = (const float*)d_in[6];
    const float* ln2_b     = (const float*)d_in[7];
    const float* time_decay= (const float*)d_in[8];
    const float* time_first= (const float*)d_in[9];
    const float* att_mix_k = (const float*)d_in[10];
    const float* att_mix_v = (const float*)d_in[11];
    const float* att_mix_r = (const float*)d_in[12];
    const float* Wk        = (const float*)d_in[13];
    const float* Wv        = (const float*)d_in[14];
    const float* Wr        = (const float*)d_in[15];
    const float* Wo        = (const float*)d_in[16];
    const float* ffn_mix_k = (const float*)d_in[17];
    const float* ffn_mix_r = (const float*)d_in[18];
    const float* Wk_f      = (const float*)d_in[19];
    const float* Wr_f      = (const float*)d_in[20];
    const float* Wv_f      = (const float*)d_in[21];

    float* out     = (float*)d_out;
    float* out_x   = out;
    float* out_wkv = out + BTC;
    float* out_tm  = out_wkv + (size_t)B_ * C_ * 3;
    float* out_cm  = out_tm + (size_t)B_ * C_;

    float *xn, *mixb, *kb, *vb, *srb, *yb, *x1, *xn2, *rb, *kvb, *kfb;
    cudaGetSymbolAddress((void**)&xn,  g_xn);
    cudaGetSymbolAddress((void**)&mixb,g_mix);
    cudaGetSymbolAddress((void**)&kb,  g_k);
    cudaGetSymbolAddress((void**)&vb,  g_v);
    cudaGetSymbolAddress((void**)&srb, g_sr);
    cudaGetSymbolAddress((void**)&yb,  g_y);
    cudaGetSymbolAddress((void**)&x1,  g_x1);
    cudaGetSymbolAddress((void**)&xn2, g_xn2);
    cudaGetSymbolAddress((void**)&rb,  g_r);
    cudaGetSymbolAddress((void**)&kvb, g_kv);
    cudaGetSymbolAddress((void**)&kfb, g_kf);

    const int M = B_ * T_;                       // 16384
    const int mixGrid = (int)(BTC / 4 / 256);    // 32768
    const dim3 gA((A_ + 127) / 128, (M + 127) / 128);   // (16,128)
    const dim3 gC((C_ + 127) / 128, (M + 127) / 128);   // (16,128)
    const dim3 gF((FF_ + 127) / 128, (M + 127) / 128);  // (64,128)

    // --- Attention half ---
    ln_kernel<<<M, 256>>>(x, ln1_g, ln1_b, xn, out_tm);

    mix_kernel<<<mixGrid, 256>>>(xn, tm_shift, att_mix_k, mixb);
    sgemm_kernel<0><<<gA, 256>>>(M, A_, C_, mixb, Wk, nullptr, kb);

    mix_kernel<<<mixGrid, 256>>>(xn, tm_shift, att_mix_v, mixb);
    sgemm_kernel<0><<<gA, 256>>>(M, A_, C_, mixb, Wv, nullptr, vb);

    mix_kernel<<<mixGrid, 256>>>(xn, tm_shift, att_mix_r, mixb);
    sgemm_kernel<1><<<gA, 256>>>(M, A_, C_, mixb, Wr, nullptr, srb);

    wkv_kernel<<<(B_ * A_ + 255) / 256, 256>>>(time_decay, time_first,
                                               kb, vb, wkv_state, yb, out_wkv);

    mul_kernel<<<mixGrid, 256>>>(srb, yb, mixb);          // sr * y
    sgemm_kernel<3><<<gC, 256>>>(M, C_, A_, mixb, Wo, x, x1);  // x1 = x + (sr*y)@Wo^T

    // --- FFN half ---
    ln_kernel<<<M, 256>>>(x1, ln2_g, ln2_b, xn2, out_cm);

    mix_kernel<<<mixGrid, 256>>>(xn2, cm_shift, ffn_mix_k, mixb);
    sgemm_kernel<2><<<gF, 256>>>(M, FF_, C_, mixb, Wk_f, nullptr, kfb); // relu^2

    mix_kernel<<<mixGrid, 256>>>(xn2, cm_shift, ffn_mix_r, mixb);
    sgemm_kernel<1><<<gC, 256>>>(M, C_, C_, mixb, Wr_f, nullptr, rb);   // sigmoid

    sgemm_kernel<0><<<gC, 256>>>(M, C_, FF_, kfb, Wv_f, nullptr, kvb);

    final_kernel<<<mixGrid, 256>>>(x1, rb, kvb, out_x);   // x = x1 + r*kv
}

// round 4
// speedup vs baseline: 5.8743x; 5.8743x over previous
#include <cuda_runtime.h>
#include <cuda_fp16.h>
#include <math.h>
#include <stdint.h>

constexpr int B_ = 4, T_ = 4096, C_ = 2048, A_ = 2048, FF_ = 8192;
constexpr int M_ = B_ * T_;                   // 16384
constexpr long BTC = (long)B_ * T_ * C_;
constexpr long BTA = (long)B_ * T_ * A_;
constexpr long BTF = (long)B_ * T_ * FF_;

// ---------------- scratch (device globals) ----------------
__device__ float  g_xn [BTC];
__device__ float  g_k  [BTA];
__device__ float  g_v  [BTA];
__device__ float  g_sr [BTA];
__device__ float  g_y  [BTA];
__device__ float  g_x1 [BTC];
__device__ float  g_xn2[BTC];
__device__ float  g_r  [BTC];
__device__ float  g_kv [BTC];
__device__ __half g_ah [BTC];            // fp16 activation buffer
__device__ __half g_kf [BTF];            // fp16 relu^2(kf)
__device__ __half g_w  [(long)FF_ * C_]; // fp16 weight buffer (reused)

// ---------------- PTX helpers ----------------
__device__ __forceinline__ uint32_t smem_u32(const void* p) {
    uint32_t a;
    asm("{ .reg .u64 t; cvta.to.shared.u64 t, %1; cvt.u32.u64 %0, t; }" : "=r"(a) : "l"(p));
    return a;
}
#define CP_ASYNC16(dst, src) \
    asm volatile("cp.async.cg.shared.global [%0], [%1], 16;" :: "r"(dst), "l"(src))
#define CP_COMMIT() asm volatile("cp.async.commit_group;" ::: "memory")
#define CP_WAIT2()  asm volatile("cp.async.wait_group 2;"  ::: "memory")

#define LDSM_X4(r0, r1, r2, r3, addr) \
    asm volatile("ldmatrix.sync.aligned.m8n8.x4.shared.b16 {%0,%1,%2,%3}, [%4];" \
                 : "=r"(r0), "=r"(r1), "=r"(r2), "=r"(r3) : "r"(addr))

#define MMA16816(c, a, b0, b1) \
    asm volatile("mma.sync.aligned.m16n8k16.row.col.f32.f16.f16.f32 " \
                 "{%0,%1,%2,%3}, {%4,%5,%6,%7}, {%8,%9}, {%0,%1,%2,%3};" \
                 : "+f"((c)[0]), "+f"((c)[1]), "+f"((c)[2]), "+f"((c)[3]) \
                 : "r"((a)[0]), "r"((a)[1]), "r"((a)[2]), "r"((a)[3]), \
                   "r"(b0), "r"(b1))

// ---------------- fp16 tensor-core GEMM ----------------
// out[m,n] = sum_k A[m,k] * W[n,k]; A,W fp16 row-major (k contiguous), acc fp32.
// CTA tile 128x128, BK=64, 4-stage cp.async, 8 warps (4m x 2n), warp tile 32x64.
constexpr int BM = 128, BN = 128, BK = 64, STAGES = 4;
constexpr uint32_t STAGE_BYTES = 32768;              // A 16KB + B 16KB
constexpr uint32_t GEMM_SMEM = STAGES * STAGE_BYTES; // 131072

__device__ __forceinline__ void load_stage(
    uint32_t st, const __half* Ab, const __half* Wb, int K, int k0, int tid)
{
    #pragma unroll
    for (int j = 0; j < 4; j++) {
        int q = tid + j * 256;
        int r = q >> 3, c = q & 7;
        CP_ASYNC16(st + r * 128 + ((c ^ (r & 7)) << 4),
                   Ab + (size_t)r * K + k0 + c * 8);
    }
    #pragma unroll
    for (int j = 0; j < 4; j++) {
        int q = tid + j * 256;
        int r = q >> 3, c = q & 7;
        CP_ASYNC16(st + 16384 + r * 128 + ((c ^ (r & 7)) << 4),
                   Wb + (size_t)r * K + k0 + c * 8);
    }
}

// EPI: 0 = fp32 out, 1 = sigmoid fp32, 2 = relu^2 -> fp16, 3 = +residual fp32
template <int EPI>
__global__ __launch_bounds__(256, 1)
void gemm_h(int K, int N,
            const __half* __restrict__ A, const __half* __restrict__ W,
            const float* __restrict__ Res, float* __restrict__ Out,
            __half* __restrict__ OutH)
{
    extern __shared__ char smem_raw[];
    const uint32_t sbase = smem_u32(smem_raw);
    const int tid = threadIdx.x;
    const int wid = tid >> 5;
    const int lane = tid & 31;
    const int wm = wid >> 1;      // 0..3
    const int wn = wid & 1;       // 0..1

    const __half* Ab = A + (size_t)blockIdx.y * BM * K;
    const __half* Wb = W + (size_t)blockIdx.x * BN * K;

    float acc[2][8][4];
    #pragma unroll
    for (int i = 0; i < 2; i++)
        #pragma unroll
        for (int j = 0; j < 8; j++)
            #pragma unroll
            for (int q = 0; q < 4; q++) acc[i][j][q] = 0.f;

    // lane-constant address components
    const int laA = lane & 15;            // A row offset
    const int caA = lane >> 4;            // A chunk offset (k-half)
    const int laB = (lane & 7) + ((lane & 16) >> 1);  // B row offset
    const int caB = (lane >> 3) & 1;      // B chunk offset

    const int NT = K / BK;
    #pragma unroll 1
    for (int s = 0; s < STAGES - 1; s++) {
        load_stage(sbase + s * STAGE_BYTES, Ab, Wb, K, s * BK, tid);
        CP_COMMIT();
    }

    #pragma unroll 1
    for (int i = 0; i < NT; i++) {
        CP_WAIT2();
        __syncthreads();

        if (i + STAGES - 1 < NT)
            load_stage(sbase + ((i + STAGES - 1) % STAGES) * STAGE_BYTES,
                       Ab, Wb, K, (i + STAGES - 1) * BK, tid);
        CP_COMMIT();

        const uint32_t As = sbase + (i % STAGES) * STAGE_BYTES;
        const uint32_t Bs = As + 16384;

        #pragma unroll
        for (int kk = 0; kk < 4; kk++) {
            uint32_t a[2][4];
            #pragma unroll
            for (int mi = 0; mi < 2; mi++) {
                const int r = wm * 32 + mi * 16 + laA;
                const int c = 2 * kk + caA;
                LDSM_X4(a[mi][0], a[mi][1], a[mi][2], a[mi][3],
                        As + r * 128 + ((c ^ (r & 7)) << 4));
            }
            uint32_t b[8][2];
            #pragma unroll
            for (int j = 0; j < 4; j++) {
                const int r = wn * 64 + 16 * j + laB;
                const int c = 2 * kk + caB;
                LDSM_X4(b[2*j][0], b[2*j][1], b[2*j+1][0], b[2*j+1][1],
                        Bs + r * 128 + ((c ^ (r & 7)) << 4));
            }
            #pragma unroll
            for (int mi = 0; mi < 2; mi++)
                #pragma unroll
                for (int j = 0; j < 8; j++)
                    MMA16816(acc[mi][j], a[mi], b[j][0], b[j][1]);
        }
    }

    // ---- epilogue ----
    const int g   = lane >> 2;
    const int tig = lane & 3;
    const size_t row0 = (size_t)blockIdx.y * BM + wm * 32;
    const size_t col0 = (size_t)blockIdx.x * BN + wn * 64;

    #pragma unroll
    for (int mi = 0; mi < 2; mi++) {
        #pragma unroll
        for (int h = 0; h < 2; h++) {
            const size_t r = row0 + mi * 16 + h * 8 + g;
            #pragma unroll
            for (int j = 0; j < 8; j++) {
                const size_t c = col0 + j * 8 + 2 * tig;
                float vx = acc[mi][j][2 * h];
                float vy = acc[mi][j][2 * h + 1];
                if (EPI == 1) {
                    vx = 1.f / (1.f + __expf(-vx));
                    vy = 1.f / (1.f + __expf(-vy));
                } else if (EPI == 3) {
                    const float2 rr = *(const float2*)(Res + r * N + c);
                    vx += rr.x; vy += rr.y;
                }
                if (EPI == 2) {
                    vx = fmaxf(vx, 0.f); vx *= vx;
                    vy = fmaxf(vy, 0.f); vy *= vy;
                    *(__half2*)(OutH + r * N + c) = __floats2half2_rn(vx, vy);
                } else {
                    *(float2*)(Out + r * N + c) = make_float2(vx, vy);
                }
            }
        }
    }
}

// ---------------- elementwise kernels ----------------
__global__ __launch_bounds__(256)
void ln_kernel(const float* __restrict__ x, const float* __restrict__ g,
               const float* __restrict__ b, float* __restrict__ out,
               float* __restrict__ shift_out)
{
    const int row = blockIdx.x;
    const float4* xr = (const float4*)(x + (size_t)row * C_);
    const int tid = threadIdx.x;

    float4 v0 = xr[tid];
    float4 v1 = xr[tid + 256];

    float s  = v0.x + v0.y + v0.z + v0.w + v1.x + v1.y + v1.z + v1.w;
    float sq = v0.x*v0.x + v0.y*v0.y + v0.z*v0.z + v0.w*v0.w
             + v1.x*v1.x + v1.y*v1.y + v1.z*v1.z + v1.w*v1.w;

    #pragma unroll
    for (int o = 16; o > 0; o >>= 1) {
        s  += __shfl_xor_sync(0xFFFFFFFFu, s,  o);
        sq += __shfl_xor_sync(0xFFFFFFFFu, sq, o);
    }
    __shared__ float ss[8], sqs[8];
    if ((tid & 31) == 0) { ss[tid >> 5] = s; sqs[tid >> 5] = sq; }
    __syncthreads();
    float ts = 0.f, tsq = 0.f;
    #pragma unroll
    for (int i = 0; i < 8; i++) { ts += ss[i]; tsq += sqs[i]; }

    const float mean = ts * (1.0f / C_);
    const float var  = tsq * (1.0f / C_) - mean * mean;
    const float rstd = rsqrtf(var + 1e-5f);

    const float4* g4 = (const float4*)g;
    const float4* b4 = (const float4*)b;
    float4 gg0 = g4[tid],       bb0 = b4[tid];
    float4 gg1 = g4[tid + 256], bb1 = b4[tid + 256];

    float4 o0, o1;
    o0.x = (v0.x - mean) * rstd * gg0.x + bb0.x;
    o0.y = (v0.y - mean) * rstd * gg0.y + bb0.y;
    o0.z = (v0.z - mean) * rstd * gg0.z + bb0.z;
    o0.w = (v0.w - mean) * rstd * gg0.w + bb0.w;
    o1.x = (v1.x - mean) * rstd * gg1.x + bb1.x;
    o1.y = (v1.y - mean) * rstd * gg1.y + bb1.y;
    o1.z = (v1.z - mean) * rstd * gg1.z + bb1.z;
    o1.w = (v1.w - mean) * rstd * gg1.w + bb1.w;

    float4* orow = (float4*)(out + (size_t)row * C_);
    orow[tid]       = o0;
    orow[tid + 256] = o1;

    if (shift_out != nullptr && (row % T_) == (T_ - 1)) {
        float4* sp2 = (float4*)(shift_out + (size_t)(row / T_) * C_);
        sp2[tid]       = o0;
        sp2[tid + 256] = o1;
    }
}

// mix (+ fp16 convert)
__global__ __launch_bounds__(256)
void mix_h_kernel(const float* __restrict__ xn, const float* __restrict__ shift,
                  const float* __restrict__ mix, __half* __restrict__ out)
{
    const long i4 = (long)blockIdx.x * 256 + threadIdx.x;
    const long e  = i4 * 4;
    const int  c4 = (int)((e % C_) >> 2);
    const long row = e / C_;
    const int  t  = (int)(row % T_);
    const int  bb = (int)(row / T_);

    float4 cur = ((const float4*)xn)[i4];
    float4 m   = ((const float4*)mix)[c4];
    float4 prev = (t == 0) ? ((const float4*)shift)[(long)bb * (C_ / 4) + c4]
                           : ((const float4*)xn)[i4 - C_ / 4];
    float4 o;
    o.x = cur.x * m.x + prev.x * (1.f - m.x);
    o.y = cur.y * m.y + prev.y * (1.f - m.y);
    o.z = cur.z * m.z + prev.z * (1.f - m.z);
    o.w = cur.w * m.w + prev.w * (1.f - m.w);
    __half2* op = (__half2*)out + i4 * 2;
    op[0] = __floats2half2_rn(o.x, o.y);
    op[1] = __floats2half2_rn(o.z, o.w);
}

// (a*b) -> fp16
__global__ __launch_bounds__(256)
void mul_h_kernel(const float* __restrict__ a, const float* __restrict__ b,
                  __half* __restrict__ out)
{
    const long i4 = (long)blockIdx.x * 256 + threadIdx.x;
    float4 x = ((const float4*)a)[i4];
    float4 y = ((const float4*)b)[i4];
    __half2* op = (__half2*)out + i4 * 2;
    op[0] = __floats2half2_rn(x.x * y.x, x.y * y.y);
    op[1] = __floats2half2_rn(x.z * y.z, x.w * y.w);
}

// fp32 -> fp16
__global__ __launch_bounds__(256)
void convh_kernel(const float* __restrict__ in, __half* __restrict__ out)
{
    const long i4 = (long)blockIdx.x * 256 + threadIdx.x;
    float4 v = ((const float4*)in)[i4];
    __half2* op = (__half2*)out + i4 * 2;
    op[0] = __floats2half2_rn(v.x, v.y);
    op[1] = __floats2half2_rn(v.z, v.w);
}

// out[i] = base[i] + r[i] * kv[i]
__global__ __launch_bounds__(256)
void final_kernel(const float* __restrict__ base, const float* __restrict__ r,
                  const float* __restrict__ kv, float* __restrict__ out)
{
    const long i4 = (long)blockIdx.x * 256 + threadIdx.x;
    float4 xb = ((const float4*)base)[i4];
    float4 xr = ((const float4*)r)[i4];
    float4 xk = ((const float4*)kv)[i4];
    float4 o;
    o.x = xb.x + xr.x * xk.x;
    o.y = xb.y + xr.y * xk.y;
    o.z = xb.z + xr.z * xk.z;
    o.w = xb.w + xr.w * xk.w;
    ((float4*)out)[i4] = o;
}

// ---------------- WKV scan ----------------
__global__ __launch_bounds__(128)
void wkv_kernel(const float* __restrict__ td, const float* __restrict__ tf,
                const float* __restrict__ k, const float* __restrict__ v,
                const float* __restrict__ state_in, float* __restrict__ y,
                float* __restrict__ state_out)
{
    const int gid = blockIdx.x * 128 + threadIdx.x;
    if (gid >= B_ * A_) return;
    const int b = gid / A_;
    const int a = gid % A_;

    const float w = -__expf(td[a]);
    const float u = tf[a];

    const size_t base = (size_t)b * T_ * A_ + a;
    const float* kp = k + base;
    const float* vp = v + base;
    float*       yp = y + base;

    const size_t si = ((size_t)b * A_ + a) * 3;
    float aa = state_in[si + 0];
    float bb = state_in[si + 1];
    float pp = state_in[si + 2];

    for (int t = 0; t < T_; t++) {
        const size_t off = (size_t)t * A_;
        const float kt = kp[off];
        const float vt = vp[off];

        float ww = u + kt;
        float p  = fmaxf(pp, ww);
        float e1 = __expf(pp - p);
        float e2 = __expf(ww - p);
        yp[off] = (e1 * aa + e2 * vt) / (e1 * bb + e2);

        ww = pp + w;
        p  = fmaxf(ww, kt);
        e1 = __expf(ww - p);
        e2 = __expf(kt - p);
        aa = e1 * aa + e2 * vt;
        bb = e1 * bb + e2;
        pp = p;
    }
    state_out[si + 0] = aa;
    state_out[si + 1] = bb;
    state_out[si + 2] = pp;
}

// ---------------- host launcher ----------------
extern "C" void kernel_launch(void* const* d_in, const int* in_sizes, int n_in,
                              void* d_out, int out_size)
{
    const float* x         = (const float*)d_in[0];
    const float* tm_shift  = (const float*)d_in[1];
    const float* wkv_state = (const float*)d_in[2];
    const float* cm_shift  = (const float*)d_in[3];
    const float* ln1_g     = (const float*)d_in[4];
    const float* ln1_b     = (const float*)d_in[5];
    const float* ln2_g     = (const float*)d_in[6];
    const float* ln2_b     = (const float*)d_in[7];
    const float* time_decay= (const float*)d_in[8];
    const float* time_first= (const float*)d_in[9];
    const float* att_mix_k = (const float*)d_in[10];
    const float* att_mix_v = (const float*)d_in[11];
    const float* att_mix_r = (const float*)d_in[12];
    const float* Wk        = (const float*)d_in[13];
    const float* Wv        = (const float*)d_in[14];
    const float* Wr        = (const float*)d_in[15];
    const float* Wo        = (const float*)d_in[16];
    const float* ffn_mix_k = (const float*)d_in[17];
    const float* ffn_mix_r = (const float*)d_in[18];
    const float* Wk_f      = (const float*)d_in[19];
    const float* Wr_f      = (const float*)d_in[20];
    const float* Wv_f      = (const float*)d_in[21];

    float* out     = (float*)d_out;
    float* out_x   = out;
    float* out_wkv = out + BTC;
    float* out_tm  = out_wkv + (size_t)B_ * C_ * 3;
    float* out_cm  = out_tm + (size_t)B_ * C_;

    float *xn, *kb, *vb, *srb, *yb, *x1, *xn2, *rb, *kvb;
    __half *ah, *kfb, *wb;
    cudaGetSymbolAddress((void**)&xn,  g_xn);
    cudaGetSymbolAddress((void**)&kb,  g_k);
    cudaGetSymbolAddress((void**)&vb,  g_v);
    cudaGetSymbolAddress((void**)&srb, g_sr);
    cudaGetSymbolAddress((void**)&yb,  g_y);
    cudaGetSymbolAddress((void**)&x1,  g_x1);
    cudaGetSymbolAddress((void**)&xn2, g_xn2);
    cudaGetSymbolAddress((void**)&rb,  g_r);
    cudaGetSymbolAddress((void**)&kvb, g_kv);
    cudaGetSymbolAddress((void**)&ah,  g_ah);
    cudaGetSymbolAddress((void**)&kfb, g_kf);
    cudaGetSymbolAddress((void**)&wb,  g_w);

    cudaFuncSetAttribute(gemm_h<0>, cudaFuncAttributeMaxDynamicSharedMemorySize, GEMM_SMEM);
    cudaFuncSetAttribute(gemm_h<1>, cudaFuncAttributeMaxDynamicSharedMemorySize, GEMM_SMEM);
    cudaFuncSetAttribute(gemm_h<2>, cudaFuncAttributeMaxDynamicSharedMemorySize, GEMM_SMEM);
    cudaFuncSetAttribute(gemm_h<3>, cudaFuncAttributeMaxDynamicSharedMemorySize, GEMM_SMEM);

    const int mixGrid = (int)(BTC / 4 / 256);            // 32768
    const int wCC = (int)((long)A_ * C_ / 4 / 256);      // 4096
    const int wFC = (int)((long)FF_ * C_ / 4 / 256);     // 16384
    const dim3 gA(A_ / BN,  M_ / BM);                    // (16, 128)
    const dim3 gC(C_ / BN,  M_ / BM);                    // (16, 128)
    const dim3 gF(FF_ / BN, M_ / BM);                    // (64, 128)

    // --- attention half ---
    ln_kernel<<<M_, 256>>>(x, ln1_g, ln1_b, xn, out_tm);

    convh_kernel<<<wCC, 256>>>(Wk, wb);
    mix_h_kernel<<<mixGrid, 256>>>(xn, tm_shift, att_mix_k, ah);
    gemm_h<0><<<gA, 256, GEMM_SMEM>>>(C_, A_, ah, wb, nullptr, kb, nullptr);

    convh_kernel<<<wCC, 256>>>(Wv, wb);
    mix_h_kernel<<<mixGrid, 256>>>(xn, tm_shift, att_mix_v, ah);
    gemm_h<0><<<gA, 256, GEMM_SMEM>>>(C_, A_, ah, wb, nullptr, vb, nullptr);

    convh_kernel<<<wCC, 256>>>(Wr, wb);
    mix_h_kernel<<<mixGrid, 256>>>(xn, tm_shift, att_mix_r, ah);
    gemm_h<1><<<gA, 256, GEMM_SMEM>>>(C_, A_, ah, wb, nullptr, srb, nullptr);

    wkv_kernel<<<(B_ * A_ + 127) / 128, 128>>>(time_decay, time_first,
                                               kb, vb, wkv_state, yb, out_wkv);

    convh_kernel<<<wCC, 256>>>(Wo, wb);
    mul_h_kernel<<<mixGrid, 256>>>(srb, yb, ah);
    gemm_h<3><<<gC, 256, GEMM_SMEM>>>(A_, C_, ah, wb, x, x1, nullptr);

    // --- FFN half ---
    ln_kernel<<<M_, 256>>>(x1, ln2_g, ln2_b, xn2, out_cm);

    convh_kernel<<<wFC, 256>>>(Wk_f, wb);
    mix_h_kernel<<<mixGrid, 256>>>(xn2, cm_shift, ffn_mix_k, ah);
    gemm_h<2><<<gF, 256, GEMM_SMEM>>>(C_, FF_, ah, wb, nullptr, nullptr, kfb);

    convh_kernel<<<wCC, 256>>>(Wr_f, wb);
    mix_h_kernel<<<mixGrid, 256>>>(xn2, cm_shift, ffn_mix_r, ah);
    gemm_h<1><<<gC, 256, GEMM_SMEM>>>(C_, C_, ah, wb, nullptr, rb, nullptr);

    convh_kernel<<<wFC, 256>>>(Wv_f, wb);
    gemm_h<0><<<gC, 256, GEMM_SMEM>>>(FF_, C_, kfb, wb, nullptr, kvb, nullptr);

    final_kernel<<<mixGrid, 256>>>(x1, rb, kvb, out_x);
}

// round 8
// speedup vs baseline: 8.0534x; 1.3710x over previous
#include <cuda_runtime.h>
#include <cuda_fp16.h>
#include <math.h>
#include <stdint.h>

constexpr int B_ = 4, T_ = 4096, C_ = 2048, A_ = 2048, FF_ = 8192;
constexpr int M_ = B_ * T_;                   // 16384
constexpr long BTC = (long)B_ * T_ * C_;
constexpr long BTA = (long)B_ * T_ * A_;
constexpr long BTF = (long)B_ * T_ * FF_;

// ---------------- scratch (device globals) ----------------
__device__ float  g_xn [BTC];
__device__ float  g_k  [BTA];
__device__ float  g_v  [BTA];
__device__ float  g_sr [BTA];
__device__ float  g_x1 [BTC];
__device__ float  g_xn2[BTC];
__device__ float  g_r  [BTC];
__device__ float  g_kv [BTC];
__device__ __half g_ah [BTC];            // fp16 activation buffer
__device__ __half g_kf [BTF];            // fp16 relu^2(kf)
__device__ __half g_w  [(long)FF_ * C_]; // fp16 weight buffer (reused)

// ---------------- PTX helpers ----------------
__device__ __forceinline__ uint32_t smem_u32(const void* p) {
    uint32_t a;
    asm("{ .reg .u64 t; cvta.to.shared.u64 t, %1; cvt.u32.u64 %0, t; }" : "=r"(a) : "l"(p));
    return a;
}
#define CP_ASYNC16(dst, src) \
    asm volatile("cp.async.cg.shared.global [%0], [%1], 16;" :: "r"(dst), "l"(src))
#define CP_COMMIT() asm volatile("cp.async.commit_group;" ::: "memory")
#define CP_WAIT2()  asm volatile("cp.async.wait_group 2;"  ::: "memory")

#define LDSM_X4(r0, r1, r2, r3, addr) \
    asm volatile("ldmatrix.sync.aligned.m8n8.x4.shared.b16 {%0,%1,%2,%3}, [%4];" \
                 : "=r"(r0), "=r"(r1), "=r"(r2), "=r"(r3) : "r"(addr))

#define MMA16816(c, a, b0, b1) \
    asm volatile("mma.sync.aligned.m16n8k16.row.col.f32.f16.f16.f32 " \
                 "{%0,%1,%2,%3}, {%4,%5,%6,%7}, {%8,%9}, {%0,%1,%2,%3};" \
                 : "+f"((c)[0]), "+f"((c)[1]), "+f"((c)[2]), "+f"((c)[3]) \
                 : "r"((a)[0]), "r"((a)[1]), "r"((a)[2]), "r"((a)[3]), \
                   "r"(b0), "r"(b1))

// ---------------- fp16 tensor-core GEMM ----------------
// out[m,n] = sum_k A[m,k] * W[n,k]; A,W fp16 row-major (k contiguous), acc fp32.
// CTA tile 128x128, BK=64, 4-stage cp.async, 8 warps (4m x 2n), warp tile 32x64.
// Register-level double buffering of ldmatrix fragments across kk steps.
constexpr int BM = 128, BN = 128, BK = 64, STAGES = 4;
constexpr uint32_t STAGE_BYTES = 32768;              // A 16KB + B 16KB
constexpr uint32_t GEMM_SMEM = STAGES * STAGE_BYTES; // 131072

__device__ __forceinline__ void load_stage(
    uint32_t st, const __half* Ab, const __half* Wb, int K, int k0, int tid)
{
    #pragma unroll
    for (int j = 0; j < 4; j++) {
        int q = tid + j * 256;
        int r = q >> 3, c = q & 7;
        CP_ASYNC16(st + r * 128 + ((c ^ (r & 7)) << 4),
                   Ab + (size_t)r * K + k0 + c * 8);
    }
    #pragma unroll
    for (int j = 0; j < 4; j++) {
        int q = tid + j * 256;
        int r = q >> 3, c = q & 7;
        CP_ASYNC16(st + 16384 + r * 128 + ((c ^ (r & 7)) << 4),
                   Wb + (size_t)r * K + k0 + c * 8);
    }
}

// EPI: 0 = fp32 out, 1 = sigmoid fp32, 2 = relu^2 -> fp16, 3 = +residual fp32
template <int EPI>
__global__ __launch_bounds__(256, 1)
void gemm_h(int K, int N,
            const __half* __restrict__ A, const __half* __restrict__ W,
            const float* __restrict__ Res, float* __restrict__ Out,
            __half* __restrict__ OutH)
{
    extern __shared__ char smem_raw[];
    const uint32_t sbase = smem_u32(smem_raw);
    const int tid = threadIdx.x;
    const int wid = tid >> 5;
    const int lane = tid & 31;
    const int wm = wid >> 1;      // 0..3
    const int wn = wid & 1;       // 0..1

    const __half* Ab = A + (size_t)blockIdx.y * BM * K;
    const __half* Wb = W + (size_t)blockIdx.x * BN * K;

    float acc[2][8][4];
    #pragma unroll
    for (int i = 0; i < 2; i++)
        #pragma unroll
        for (int j = 0; j < 8; j++)
            #pragma unroll
            for (int q = 0; q < 4; q++) acc[i][j][q] = 0.f;

    // lane-constant address components
    const int laA = lane & 15;            // A row offset
    const int caA = lane >> 4;            // A chunk offset (k-half)
    const int laB = (lane & 7) + ((lane & 16) >> 1);  // B row offset
    const int caB = (lane >> 3) & 1;      // B chunk offset
    const int rA = wm * 32 + laA;         // +mi*16
    const int rB = wn * 64 + laB;         // +16*j

    const int NT = K / BK;
    #pragma unroll 1
    for (int s = 0; s < STAGES - 1; s++) {
        load_stage(sbase + s * STAGE_BYTES, Ab, Wb, K, s * BK, tid);
        CP_COMMIT();
    }

    uint32_t afrag[2][2][4];   // [buf][mi][4]
    uint32_t bfrag[2][8][2];   // [buf][j][2]

    #pragma unroll 1
    for (int i = 0; i < NT; i++) {
        CP_WAIT2();
        __syncthreads();

        if (i + STAGES - 1 < NT)
            load_stage(sbase + ((i + STAGES - 1) % STAGES) * STAGE_BYTES,
                       Ab, Wb, K, (i + STAGES - 1) * BK, tid);
        CP_COMMIT();

        const uint32_t As = sbase + (i % STAGES) * STAGE_BYTES;
        const uint32_t Bs = As + 16384;

        // prologue: fragments for kk=0
        {
            const int c0 = caA;
            #pragma unroll
            for (int mi = 0; mi < 2; mi++) {
                const int r = rA + mi * 16;
                LDSM_X4(afrag[0][mi][0], afrag[0][mi][1], afrag[0][mi][2], afrag[0][mi][3],
                        As + r * 128 + ((c0 ^ (r & 7)) << 4));
            }
            const int c1 = caB;
            #pragma unroll
            for (int j = 0; j < 4; j++) {
                const int r = rB + 16 * j;
                LDSM_X4(bfrag[0][2*j][0], bfrag[0][2*j][1], bfrag[0][2*j+1][0], bfrag[0][2*j+1][1],
                        Bs + r * 128 + ((c1 ^ (r & 7)) << 4));
            }
        }

        #pragma unroll
        for (int kk = 0; kk < 4; kk++) {
            const int cur = kk & 1, nxt = cur ^ 1;
            if (kk < 3) {
                const int c0 = 2 * (kk + 1) + caA;
                #pragma unroll
                for (int mi = 0; mi < 2; mi++) {
                    const int r = rA + mi * 16;
                    LDSM_X4(afrag[nxt][mi][0], afrag[nxt][mi][1],
                            afrag[nxt][mi][2], afrag[nxt][mi][3],
                            As + r * 128 + ((c0 ^ (r & 7)) << 4));
                }
                const int c1 = 2 * (kk + 1) + caB;
                #pragma unroll
                for (int j = 0; j < 4; j++) {
                    const int r = rB + 16 * j;
                    LDSM_X4(bfrag[nxt][2*j][0], bfrag[nxt][2*j][1],
                            bfrag[nxt][2*j+1][0], bfrag[nxt][2*j+1][1],
                            Bs + r * 128 + ((c1 ^ (r & 7)) << 4));
                }
            }
            #pragma unroll
            for (int mi = 0; mi < 2; mi++)
                #pragma unroll
                for (int j = 0; j < 8; j++)
                    MMA16816(acc[mi][j], afrag[cur][mi], bfrag[cur][j][0], bfrag[cur][j][1]);
        }
    }

    // ---- epilogue ----
    const int g   = lane >> 2;
    const int tig = lane & 3;
    const size_t row0 = (size_t)blockIdx.y * BM + wm * 32;
    const size_t col0 = (size_t)blockIdx.x * BN + wn * 64;

    #pragma unroll
    for (int mi = 0; mi < 2; mi++) {
        #pragma unroll
        for (int h = 0; h < 2; h++) {
            const size_t r = row0 + mi * 16 + h * 8 + g;
            #pragma unroll
            for (int j = 0; j < 8; j++) {
                const size_t c = col0 + j * 8 + 2 * tig;
                float vx = acc[mi][j][2 * h];
                float vy = acc[mi][j][2 * h + 1];
                if (EPI == 1) {
                    vx = 1.f / (1.f + __expf(-vx));
                    vy = 1.f / (1.f + __expf(-vy));
                } else if (EPI == 3) {
                    const float2 rr = *(const float2*)(Res + r * N + c);
                    vx += rr.x; vy += rr.y;
                }
                if (EPI == 2) {
                    vx = fmaxf(vx, 0.f); vx *= vx;
                    vy = fmaxf(vy, 0.f); vy *= vy;
                    *(__half2*)(OutH + r * N + c) = __floats2half2_rn(vx, vy);
                } else {
                    *(float2*)(Out + r * N + c) = make_float2(vx, vy);
                }
            }
        }
    }
}

// ---------------- elementwise kernels ----------------
__global__ __launch_bounds__(256)
void ln_kernel(const float* __restrict__ x, const float* __restrict__ g,
               const float* __restrict__ b, float* __restrict__ out,
               float* __restrict__ shift_out)
{
    const int row = blockIdx.x;
    const float4* xr = (const float4*)(x + (size_t)row * C_);
    const int tid = threadIdx.x;

    float4 v0 = xr[tid];
    float4 v1 = xr[tid + 256];

    float s  = v0.x + v0.y + v0.z + v0.w + v1.x + v1.y + v1.z + v1.w;
    float sq = v0.x*v0.x + v0.y*v0.y + v0.z*v0.z + v0.w*v0.w
             + v1.x*v1.x + v1.y*v1.y + v1.z*v1.z + v1.w*v1.w;

    #pragma unroll
    for (int o = 16; o > 0; o >>= 1) {
        s  += __shfl_xor_sync(0xFFFFFFFFu, s,  o);
        sq += __shfl_xor_sync(0xFFFFFFFFu, sq, o);
    }
    __shared__ float ss[8], sqs[8];
    if ((tid & 31) == 0) { ss[tid >> 5] = s; sqs[tid >> 5] = sq; }
    __syncthreads();
    float ts = 0.f, tsq = 0.f;
    #pragma unroll
    for (int i = 0; i < 8; i++) { ts += ss[i]; tsq += sqs[i]; }

    const float mean = ts * (1.0f / C_);
    const float var  = tsq * (1.0f / C_) - mean * mean;
    const float rstd = rsqrtf(var + 1e-5f);

    const float4* g4 = (const float4*)g;
    const float4* b4 = (const float4*)b;
    float4 gg0 = g4[tid],       bb0 = b4[tid];
    float4 gg1 = g4[tid + 256], bb1 = b4[tid + 256];

    float4 o0, o1;
    o0.x = (v0.x - mean) * rstd * gg0.x + bb0.x;
    o0.y = (v0.y - mean) * rstd * gg0.y + bb0.y;
    o0.z = (v0.z - mean) * rstd * gg0.z + bb0.z;
    o0.w = (v0.w - mean) * rstd * gg0.w + bb0.w;
    o1.x = (v1.x - mean) * rstd * gg1.x + bb1.x;
    o1.y = (v1.y - mean) * rstd * gg1.y + bb1.y;
    o1.z = (v1.z - mean) * rstd * gg1.z + bb1.z;
    o1.w = (v1.w - mean) * rstd * gg1.w + bb1.w;

    float4* orow = (float4*)(out + (size_t)row * C_);
    orow[tid]       = o0;
    orow[tid + 256] = o1;

    if (shift_out != nullptr && (row % T_) == (T_ - 1)) {
        float4* sp2 = (float4*)(shift_out + (size_t)(row / T_) * C_);
        sp2[tid]       = o0;
        sp2[tid + 256] = o1;
    }
}

// mix (+ fp16 convert)
__global__ __launch_bounds__(256)
void mix_h_kernel(const float* __restrict__ xn, const float* __restrict__ shift,
                  const float* __restrict__ mix, __half* __restrict__ out)
{
    const long i4 = (long)blockIdx.x * 256 + threadIdx.x;
    const long e  = i4 * 4;
    const int  c4 = (int)((e % C_) >> 2);
    const long row = e / C_;
    const int  t  = (int)(row % T_);
    const int  bb = (int)(row / T_);

    float4 cur = ((const float4*)xn)[i4];
    float4 m   = ((const float4*)mix)[c4];
    float4 prev = (t == 0) ? ((const float4*)shift)[(long)bb * (C_ / 4) + c4]
                           : ((const float4*)xn)[i4 - C_ / 4];
    float4 o;
    o.x = cur.x * m.x + prev.x * (1.f - m.x);
    o.y = cur.y * m.y + prev.y * (1.f - m.y);
    o.z = cur.z * m.z + prev.z * (1.f - m.z);
    o.w = cur.w * m.w + prev.w * (1.f - m.w);
    __half2* op = (__half2*)out + i4 * 2;
    op[0] = __floats2half2_rn(o.x, o.y);
    op[1] = __floats2half2_rn(o.z, o.w);
}

// fp32 -> fp16
__global__ __launch_bounds__(256)
void convh_kernel(const float* __restrict__ in, __half* __restrict__ out)
{
    const long i4 = (long)blockIdx.x * 256 + threadIdx.x;
    float4 v = ((const float4*)in)[i4];
    __half2* op = (__half2*)out + i4 * 2;
    op[0] = __floats2half2_rn(v.x, v.y);
    op[1] = __floats2half2_rn(v.z, v.w);
}

// out[i] = base[i] + r[i] * kv[i]
__global__ __launch_bounds__(256)
void final_kernel(const float* __restrict__ base, const float* __restrict__ r,
                  const float* __restrict__ kv, float* __restrict__ out)
{
    const long i4 = (long)blockIdx.x * 256 + threadIdx.x;
    float4 xb = ((const float4*)base)[i4];
    float4 xr = ((const float4*)r)[i4];
    float4 xk = ((const float4*)kv)[i4];
    float4 o;
    o.x = xb.x + xr.x * xk.x;
    o.y = xb.y + xr.y * xk.y;
    o.z = xb.z + xr.z * xk.z;
    o.w = xb.w + xr.w * xk.w;
    ((float4*)out)[i4] = o;
}

// ---------------- WKV scan (software-pipelined, fuses sr*y -> fp16) ----------
constexpr int WU = 8;   // unroll / prefetch group
__global__ __launch_bounds__(128)
void wkv_kernel(const float* __restrict__ td, const float* __restrict__ tf,
                const float* __restrict__ k, const float* __restrict__ v,
                const float* __restrict__ sr, const float* __restrict__ state_in,
                __half* __restrict__ ah, float* __restrict__ state_out)
{
    const int gid = blockIdx.x * 128 + threadIdx.x;
    if (gid >= B_ * A_) return;
    const int b = gid / A_;
    const int a = gid % A_;

    const float w = -__expf(td[a]);
    const float u = tf[a];

    const size_t base = (size_t)b * T_ * A_ + a;
    const float* kp = k + base;
    const float* vp = v + base;
    const float* sp = sr + base;
    __half*      yp = ah + base;

    const size_t si = ((size_t)b * A_ + a) * 3;
    float aa = state_in[si + 0];
    float bb = state_in[si + 1];
    float pp = state_in[si + 2];

    float ka[WU], va[WU], sa[WU];
    float kn[WU], vn[WU], sn[WU];
    #pragma unroll
    for (int j = 0; j < WU; j++) {
        ka[j] = kp[(size_t)j * A_];
        va[j] = vp[(size_t)j * A_];
        sa[j] = sp[(size_t)j * A_];
    }

    constexpr int NG = T_ / WU;
    #pragma unroll 1
    for (int g = 0; g < NG; g++) {
        if (g + 1 < NG) {
            const size_t o = (size_t)(g + 1) * WU * A_;
            #pragma unroll
            for (int j = 0; j < WU; j++) {
                kn[j] = kp[o + (size_t)j * A_];
                vn[j] = vp[o + (size_t)j * A_];
                sn[j] = sp[o + (size_t)j * A_];
            }
        }
        const size_t yo = (size_t)g * WU * A_;
        #pragma unroll
        for (int j = 0; j < WU; j++) {
            const float kt = ka[j];
            const float vt = va[j];

            float ww = u + kt;
            float p  = fmaxf(pp, ww);
            float e1 = __expf(pp - p);
            float e2 = __expf(ww - p);
            const float y = (e1 * aa + e2 * vt) / (e1 * bb + e2);
            yp[yo + (size_t)j * A_] = __float2half(sa[j] * y);

            ww = pp + w;
            p  = fmaxf(ww, kt);
            e1 = __expf(ww - p);
            e2 = __expf(kt - p);
            aa = e1 * aa + e2 * vt;
            bb = e1 * bb + e2;
            pp = p;
        }
        #pragma unroll
        for (int j = 0; j < WU; j++) { ka[j] = kn[j]; va[j] = vn[j]; sa[j] = sn[j]; }
    }
    state_out[si + 0] = aa;
    state_out[si + 1] = bb;
    state_out[si + 2] = pp;
}

// ---------------- host launcher ----------------
extern "C" void kernel_launch(void* const* d_in, const int* in_sizes, int n_in,
                              void* d_out, int out_size)
{
    const float* x         = (const float*)d_in[0];
    const float* tm_shift  = (const float*)d_in[1];
    const float* wkv_state = (const float*)d_in[2];
    const float* cm_shift  = (const float*)d_in[3];
    const float* ln1_g     = (const float*)d_in[4];
    const float* ln1_b     = (const float*)d_in[5];
    const float* ln2_g     = (const float*)d_in[6];
    const float* ln2_b     = (const float*)d_in[7];
    const float* time_decay= (const float*)d_in[8];
    const float* time_first= (const float*)d_in[9];
    const float* att_mix_k = (const float*)d_in[10];
    const float* att_mix_v = (const float*)d_in[11];
    const float* att_mix_r = (const float*)d_in[12];
    const float* Wk        = (const float*)d_in[13];
    const float* Wv        = (const float*)d_in[14];
    const float* Wr        = (const float*)d_in[15];
    const float* Wo        = (const float*)d_in[16];
    const float* ffn_mix_k = (const float*)d_in[17];
    const float* ffn_mix_r = (const float*)d_in[18];
    const float* Wk_f      = (const float*)d_in[19];
    const float* Wr_f      = (const float*)d_in[20];
    const float* Wv_f      = (const float*)d_in[21];

    float* out     = (float*)d_out;
    float* out_x   = out;
    float* out_wkv = out + BTC;
    float* out_tm  = out_wkv + (size_t)B_ * C_ * 3;
    float* out_cm  = out_tm + (size_t)B_ * C_;

    float *xn, *kb, *vb, *srb, *x1, *xn2, *rb, *kvb;
    __half *ah, *kfb, *wb;
    cudaGetSymbolAddress((void**)&xn,  g_xn);
    cudaGetSymbolAddress((void**)&kb,  g_k);
    cudaGetSymbolAddress((void**)&vb,  g_v);
    cudaGetSymbolAddress((void**)&srb, g_sr);
    cudaGetSymbolAddress((void**)&x1,  g_x1);
    cudaGetSymbolAddress((void**)&xn2, g_xn2);
    cudaGetSymbolAddress((void**)&rb,  g_r);
    cudaGetSymbolAddress((void**)&kvb, g_kv);
    cudaGetSymbolAddress((void**)&ah,  g_ah);
    cudaGetSymbolAddress((void**)&kfb, g_kf);
    cudaGetSymbolAddress((void**)&wb,  g_w);

    cudaFuncSetAttribute(gemm_h<0>, cudaFuncAttributeMaxDynamicSharedMemorySize, GEMM_SMEM);
    cudaFuncSetAttribute(gemm_h<1>, cudaFuncAttributeMaxDynamicSharedMemorySize, GEMM_SMEM);
    cudaFuncSetAttribute(gemm_h<2>, cudaFuncAttributeMaxDynamicSharedMemorySize, GEMM_SMEM);
    cudaFuncSetAttribute(gemm_h<3>, cudaFuncAttributeMaxDynamicSharedMemorySize, GEMM_SMEM);

    const int mixGrid = (int)(BTC / 4 / 256);            // 32768
    const int wCC = (int)((long)A_ * C_ / 4 / 256);      // 4096
    const int wFC = (int)((long)FF_ * C_ / 4 / 256);     // 16384
    const dim3 gA(A_ / BN,  M_ / BM);                    // (16, 128)
    const dim3 gC(C_ / BN,  M_ / BM);                    // (16, 128)
    const dim3 gF(FF_ / BN, M_ / BM);                    // (64, 128)

    // --- attention half ---
    ln_kernel<<<M_, 256>>>(x, ln1_g, ln1_b, xn, out_tm);

    convh_kernel<<<wCC, 256>>>(Wk, wb);
    mix_h_kernel<<<mixGrid, 256>>>(xn, tm_shift, att_mix_k, ah);
    gemm_h<0><<<gA, 256, GEMM_SMEM>>>(C_, A_, ah, wb, nullptr, kb, nullptr);

    convh_kernel<<<wCC, 256>>>(Wv, wb);
    mix_h_kernel<<<mixGrid, 256>>>(xn, tm_shift, att_mix_v, ah);
    gemm_h<0><<<gA, 256, GEMM_SMEM>>>(C_, A_, ah, wb, nullptr, vb, nullptr);

    convh_kernel<<<wCC, 256>>>(Wr, wb);
    mix_h_kernel<<<mixGrid, 256>>>(xn, tm_shift, att_mix_r, ah);
    gemm_h<1><<<gA, 256, GEMM_SMEM>>>(C_, A_, ah, wb, nullptr, srb, nullptr);

    // wkv scan: writes ah = fp16(sr * y) directly
    wkv_kernel<<<(B_ * A_ + 127) / 128, 128>>>(time_decay, time_first,
                                               kb, vb, srb, wkv_state, ah, out_wkv);

    convh_kernel<<<wCC, 256>>>(Wo, wb);
    gemm_h<3><<<gC, 256, GEMM_SMEM>>>(A_, C_, ah, wb, x, x1, nullptr);

    // --- FFN half ---
    ln_kernel<<<M_, 256>>>(x1, ln2_g, ln2_b, xn2, out_cm);

    convh_kernel<<<wFC, 256>>>(Wk_f, wb);
    mix_h_kernel<<<mixGrid, 256>>>(xn2, cm_shift, ffn_mix_k, ah);
    gemm_h<2><<<gF, 256, GEMM_SMEM>>>(C_, FF_, ah, wb, nullptr, nullptr, kfb);

    convh_kernel<<<wCC, 256>>>(Wr_f, wb);
    mix_h_kernel<<<mixGrid, 256>>>(xn2, cm_shift, ffn_mix_r, ah);
    gemm_h<1><<<gC, 256, GEMM_SMEM>>>(C_, C_, ah, wb, nullptr, rb, nullptr);

    convh_kernel<<<wFC, 256>>>(Wv_f, wb);
    gemm_h<0><<<gC, 256, GEMM_SMEM>>>(FF_, C_, kfb, wb, nullptr, kvb, nullptr);

    final_kernel<<<mixGrid, 256>>>(x1, rb, kvb, out_x);
}

// round 9
// speedup vs baseline: 9.3695x; 1.1634x over previous
#include <cuda_runtime.h>
#include <cuda_fp16.h>
#include <math.h>
#include <stdint.h>

constexpr int B_ = 4, T_ = 4096, C_ = 2048, A_ = 2048, FF_ = 8192;
constexpr int M_ = B_ * T_;                   // 16384
constexpr long BTC = (long)B_ * T_ * C_;
constexpr long BTA = (long)B_ * T_ * A_;
constexpr long BTF = (long)B_ * T_ * FF_;

// ---------------- scratch (device globals) ----------------
__device__ float  g_xn [BTC];
__device__ float  g_k  [BTA];
__device__ float  g_v  [BTA];
__device__ float  g_sr [BTA];
__device__ float  g_x1 [BTC];
__device__ float  g_xn2[BTC];
__device__ float  g_r  [BTC];
__device__ float  g_kv [BTC];
__device__ __half g_ah [BTC];            // fp16 activation buffer
__device__ __half g_kf [BTF];            // fp16 relu^2(kf)
__device__ __half g_w  [(long)FF_ * C_]; // fp16 weight buffer (reused)

// ---------------- PTX helpers ----------------
__device__ __forceinline__ uint32_t smem_u32(const void* p) {
    uint32_t a;
    asm("{ .reg .u64 t; cvta.to.shared.u64 t, %1; cvt.u32.u64 %0, t; }" : "=r"(a) : "l"(p));
    return a;
}
#define CP_ASYNC16(dst, src) \
    asm volatile("cp.async.cg.shared.global [%0], [%1], 16;" :: "r"(dst), "l"(src))
#define CP_COMMIT() asm volatile("cp.async.commit_group;" ::: "memory")
#define CP_WAIT1()  asm volatile("cp.async.wait_group 1;"  ::: "memory")

#define LDSM_X4(r0, r1, r2, r3, addr) \
    asm volatile("ldmatrix.sync.aligned.m8n8.x4.shared.b16 {%0,%1,%2,%3}, [%4];" \
                 : "=r"(r0), "=r"(r1), "=r"(r2), "=r"(r3) : "r"(addr))

#define MMA16816(c, a, b0, b1) \
    asm volatile("mma.sync.aligned.m16n8k16.row.col.f32.f16.f16.f32 " \
                 "{%0,%1,%2,%3}, {%4,%5,%6,%7}, {%8,%9}, {%0,%1,%2,%3};" \
                 : "+f"((c)[0]), "+f"((c)[1]), "+f"((c)[2]), "+f"((c)[3]) \
                 : "r"((a)[0]), "r"((a)[1]), "r"((a)[2]), "r"((a)[3]), \
                   "r"(b0), "r"(b1))

// ---------------- fp16 tensor-core GEMM ----------------
// out[m,n] = sum_k A[m,k] * W[n,k]; A,W fp16 row-major (k contiguous), acc fp32.
// CTA tile 128x128, BK=64, 3-stage cp.async, 8 warps (4m x 2n), warp tile 32x64.
// 2 CTAs / SM (96KB smem each) to cover sync/LDSM bubbles.
constexpr int BM = 128, BN = 128, BK = 64, STAGES = 3;
constexpr uint32_t STAGE_BYTES = 32768;              // A 16KB + B 16KB
constexpr uint32_t GEMM_SMEM = STAGES * STAGE_BYTES; // 98304

__device__ __forceinline__ void load_stage(
    uint32_t st, const __half* Ab, const __half* Wb, int K, int k0, int tid)
{
    #pragma unroll
    for (int j = 0; j < 4; j++) {
        int q = tid + j * 256;
        int r = q >> 3, c = q & 7;
        CP_ASYNC16(st + r * 128 + ((c ^ (r & 7)) << 4),
                   Ab + (size_t)r * K + k0 + c * 8);
    }
    #pragma unroll
    for (int j = 0; j < 4; j++) {
        int q = tid + j * 256;
        int r = q >> 3, c = q & 7;
        CP_ASYNC16(st + 16384 + r * 128 + ((c ^ (r & 7)) << 4),
                   Wb + (size_t)r * K + k0 + c * 8);
    }
}

// EPI: 0 = fp32 out, 1 = sigmoid fp32, 2 = relu^2 -> fp16, 3 = +residual fp32
template <int EPI>
__global__ __launch_bounds__(256, 2)
void gemm_h(int K, int N,
            const __half* __restrict__ A, const __half* __restrict__ W,
            const float* __restrict__ Res, float* __restrict__ Out,
            __half* __restrict__ OutH)
{
    extern __shared__ char smem_raw[];
    const uint32_t sbase = smem_u32(smem_raw);
    const int tid = threadIdx.x;
    const int wid = tid >> 5;
    const int lane = tid & 31;
    const int wm = wid >> 1;      // 0..3
    const int wn = wid & 1;       // 0..1

    const __half* Ab = A + (size_t)blockIdx.y * BM * K;
    const __half* Wb = W + (size_t)blockIdx.x * BN * K;

    float acc[2][8][4];
    #pragma unroll
    for (int i = 0; i < 2; i++)
        #pragma unroll
        for (int j = 0; j < 8; j++)
            #pragma unroll
            for (int q = 0; q < 4; q++) acc[i][j][q] = 0.f;

    // lane-constant address components
    const int laA = lane & 15;            // A row offset
    const int caA = lane >> 4;            // A chunk offset (k-half)
    const int laB = (lane & 7) + ((lane & 16) >> 1);  // B row offset
    const int caB = (lane >> 3) & 1;      // B chunk offset
    const int rA = wm * 32 + laA;         // +mi*16
    const int rB = wn * 64 + laB;         // +16*j

    const int NT = K / BK;
    #pragma unroll 1
    for (int s = 0; s < STAGES - 1; s++) {
        load_stage(sbase + s * STAGE_BYTES, Ab, Wb, K, s * BK, tid);
        CP_COMMIT();
    }

    #pragma unroll 1
    for (int i = 0; i < NT; i++) {
        CP_WAIT1();
        __syncthreads();

        if (i + STAGES - 1 < NT)
            load_stage(sbase + ((i + STAGES - 1) % STAGES) * STAGE_BYTES,
                       Ab, Wb, K, (i + STAGES - 1) * BK, tid);
        CP_COMMIT();

        const uint32_t As = sbase + (i % STAGES) * STAGE_BYTES;
        const uint32_t Bs = As + 16384;

        #pragma unroll
        for (int kk = 0; kk < 4; kk++) {
            uint32_t a[2][4];
            #pragma unroll
            for (int mi = 0; mi < 2; mi++) {
                const int r = rA + mi * 16;
                const int c = 2 * kk + caA;
                LDSM_X4(a[mi][0], a[mi][1], a[mi][2], a[mi][3],
                        As + r * 128 + ((c ^ (r & 7)) << 4));
            }
            uint32_t b[8][2];
            #pragma unroll
            for (int j = 0; j < 4; j++) {
                const int r = rB + 16 * j;
                const int c = 2 * kk + caB;
                LDSM_X4(b[2*j][0], b[2*j][1], b[2*j+1][0], b[2*j+1][1],
                        Bs + r * 128 + ((c ^ (r & 7)) << 4));
            }
            #pragma unroll
            for (int mi = 0; mi < 2; mi++)
                #pragma unroll
                for (int j = 0; j < 8; j++)
                    MMA16816(acc[mi][j], a[mi], b[j][0], b[j][1]);
        }
    }

    // ---- epilogue ----
    const int g   = lane >> 2;
    const int tig = lane & 3;
    const size_t row0 = (size_t)blockIdx.y * BM + wm * 32;
    const size_t col0 = (size_t)blockIdx.x * BN + wn * 64;

    #pragma unroll
    for (int mi = 0; mi < 2; mi++) {
        #pragma unroll
        for (int h = 0; h < 2; h++) {
            const size_t r = row0 + mi * 16 + h * 8 + g;
            #pragma unroll
            for (int j = 0; j < 8; j++) {
                const size_t c = col0 + j * 8 + 2 * tig;
                float vx = acc[mi][j][2 * h];
                float vy = acc[mi][j][2 * h + 1];
                if (EPI == 1) {
                    vx = 1.f / (1.f + __expf(-vx));
                    vy = 1.f / (1.f + __expf(-vy));
                } else if (EPI == 3) {
                    const float2 rr = *(const float2*)(Res + r * N + c);
                    vx += rr.x; vy += rr.y;
                }
                if (EPI == 2) {
                    vx = fmaxf(vx, 0.f); vx *= vx;
                    vy = fmaxf(vy, 0.f); vy *= vy;
                    *(__half2*)(OutH + r * N + c) = __floats2half2_rn(vx, vy);
                } else {
                    *(float2*)(Out + r * N + c) = make_float2(vx, vy);
                }
            }
        }
    }
}

// ---------------- elementwise kernels ----------------
__global__ __launch_bounds__(256)
void ln_kernel(const float* __restrict__ x, const float* __restrict__ g,
               const float* __restrict__ b, float* __restrict__ out,
               float* __restrict__ shift_out)
{
    const int row = blockIdx.x;
    const float4* xr = (const float4*)(x + (size_t)row * C_);
    const int tid = threadIdx.x;

    float4 v0 = xr[tid];
    float4 v1 = xr[tid + 256];

    float s  = v0.x + v0.y + v0.z + v0.w + v1.x + v1.y + v1.z + v1.w;
    float sq = v0.x*v0.x + v0.y*v0.y + v0.z*v0.z + v0.w*v0.w
             + v1.x*v1.x + v1.y*v1.y + v1.z*v1.z + v1.w*v1.w;

    #pragma unroll
    for (int o = 16; o > 0; o >>= 1) {
        s  += __shfl_xor_sync(0xFFFFFFFFu, s,  o);
        sq += __shfl_xor_sync(0xFFFFFFFFu, sq, o);
    }
    __shared__ float ss[8], sqs[8];
    if ((tid & 31) == 0) { ss[tid >> 5] = s; sqs[tid >> 5] = sq; }
    __syncthreads();
    float ts = 0.f, tsq = 0.f;
    #pragma unroll
    for (int i = 0; i < 8; i++) { ts += ss[i]; tsq += sqs[i]; }

    const float mean = ts * (1.0f / C_);
    const float var  = tsq * (1.0f / C_) - mean * mean;
    const float rstd = rsqrtf(var + 1e-5f);

    const float4* g4 = (const float4*)g;
    const float4* b4 = (const float4*)b;
    float4 gg0 = g4[tid],       bb0 = b4[tid];
    float4 gg1 = g4[tid + 256], bb1 = b4[tid + 256];

    float4 o0, o1;
    o0.x = (v0.x - mean) * rstd * gg0.x + bb0.x;
    o0.y = (v0.y - mean) * rstd * gg0.y + bb0.y;
    o0.z = (v0.z - mean) * rstd * gg0.z + bb0.z;
    o0.w = (v0.w - mean) * rstd * gg0.w + bb0.w;
    o1.x = (v1.x - mean) * rstd * gg1.x + bb1.x;
    o1.y = (v1.y - mean) * rstd * gg1.y + bb1.y;
    o1.z = (v1.z - mean) * rstd * gg1.z + bb1.z;
    o1.w = (v1.w - mean) * rstd * gg1.w + bb1.w;

    float4* orow = (float4*)(out + (size_t)row * C_);
    orow[tid]       = o0;
    orow[tid + 256] = o1;

    if (shift_out != nullptr && (row % T_) == (T_ - 1)) {
        float4* sp2 = (float4*)(shift_out + (size_t)(row / T_) * C_);
        sp2[tid]       = o0;
        sp2[tid + 256] = o1;
    }
}

// mix (+ fp16 convert)
__global__ __launch_bounds__(256)
void mix_h_kernel(const float* __restrict__ xn, const float* __restrict__ shift,
                  const float* __restrict__ mix, __half* __restrict__ out)
{
    const long i4 = (long)blockIdx.x * 256 + threadIdx.x;
    const long e  = i4 * 4;
    const int  c4 = (int)((e % C_) >> 2);
    const long row = e / C_;
    const int  t  = (int)(row % T_);
    const int  bb = (int)(row / T_);

    float4 cur = ((const float4*)xn)[i4];
    float4 m   = ((const float4*)mix)[c4];
    float4 prev = (t == 0) ? ((const float4*)shift)[(long)bb * (C_ / 4) + c4]
                           : ((const float4*)xn)[i4 - C_ / 4];
    float4 o;
    o.x = cur.x * m.x + prev.x * (1.f - m.x);
    o.y = cur.y * m.y + prev.y * (1.f - m.y);
    o.z = cur.z * m.z + prev.z * (1.f - m.z);
    o.w = cur.w * m.w + prev.w * (1.f - m.w);
    __half2* op = (__half2*)out + i4 * 2;
    op[0] = __floats2half2_rn(o.x, o.y);
    op[1] = __floats2half2_rn(o.z, o.w);
}

// fp32 -> fp16
__global__ __launch_bounds__(256)
void convh_kernel(const float* __restrict__ in, __half* __restrict__ out)
{
    const long i4 = (long)blockIdx.x * 256 + threadIdx.x;
    float4 v = ((const float4*)in)[i4];
    __half2* op = (__half2*)out + i4 * 2;
    op[0] = __floats2half2_rn(v.x, v.y);
    op[1] = __floats2half2_rn(v.z, v.w);
}

// out[i] = base[i] + r[i] * kv[i]
__global__ __launch_bounds__(256)
void final_kernel(const float* __restrict__ base, const float* __restrict__ r,
                  const float* __restrict__ kv, float* __restrict__ out)
{
    const long i4 = (long)blockIdx.x * 256 + threadIdx.x;
    float4 xb = ((const float4*)base)[i4];
    float4 xr = ((const float4*)r)[i4];
    float4 xk = ((const float4*)kv)[i4];
    float4 o;
    o.x = xb.x + xr.x * xk.x;
    o.y = xb.y + xr.y * xk.y;
    o.z = xb.z + xr.z * xk.z;
    o.w = xb.w + xr.w * xk.w;
    ((float4*)out)[i4] = o;
}

// ---------------- WKV scan (software-pipelined, fuses sr*y -> fp16) ----------
constexpr int WU = 8;   // unroll / prefetch group
__global__ __launch_bounds__(64)
void wkv_kernel(const float* __restrict__ td, const float* __restrict__ tf,
                const float* __restrict__ k, const float* __restrict__ v,
                const float* __restrict__ sr, const float* __restrict__ state_in,
                __half* __restrict__ ah, float* __restrict__ state_out)
{
    const int gid = blockIdx.x * 64 + threadIdx.x;
    if (gid >= B_ * A_) return;
    const int b = gid / A_;
    const int a = gid % A_;

    const float w = -__expf(td[a]);
    const float u = tf[a];

    const size_t base = (size_t)b * T_ * A_ + a;
    const float* kp = k + base;
    const float* vp = v + base;
    const float* sp = sr + base;
    __half*      yp = ah + base;

    const size_t si = ((size_t)b * A_ + a) * 3;
    float aa = state_in[si + 0];
    float bb = state_in[si + 1];
    float pp = state_in[si + 2];

    float ka[WU], va[WU], sa[WU];
    float kn[WU], vn[WU], sn[WU];
    #pragma unroll
    for (int j = 0; j < WU; j++) {
        ka[j] = kp[(size_t)j * A_];
        va[j] = vp[(size_t)j * A_];
        sa[j] = sp[(size_t)j * A_];
    }

    constexpr int NG = T_ / WU;
    #pragma unroll 1
    for (int g = 0; g < NG; g++) {
        if (g + 1 < NG) {
            const size_t o = (size_t)(g + 1) * WU * A_;
            #pragma unroll
            for (int j = 0; j < WU; j++) {
                kn[j] = kp[o + (size_t)j * A_];
                vn[j] = vp[o + (size_t)j * A_];
                sn[j] = sp[o + (size_t)j * A_];
            }
        }
        const size_t yo = (size_t)g * WU * A_;
        #pragma unroll
        for (int j = 0; j < WU; j++) {
            const float kt = ka[j];
            const float vt = va[j];

            float ww = u + kt;
            float p  = fmaxf(pp, ww);
            float e1 = __expf(pp - p);
            float e2 = __expf(ww - p);
            const float y = (e1 * aa + e2 * vt) / (e1 * bb + e2);
            yp[yo + (size_t)j * A_] = __float2half(sa[j] * y);

            ww = pp + w;
            p  = fmaxf(ww, kt);
            e1 = __expf(ww - p);
            e2 = __expf(kt - p);
            aa = e1 * aa + e2 * vt;
            bb = e1 * bb + e2;
            pp = p;
        }
        #pragma unroll
        for (int j = 0; j < WU; j++) { ka[j] = kn[j]; va[j] = vn[j]; sa[j] = sn[j]; }
    }
    state_out[si + 0] = aa;
    state_out[si + 1] = bb;
    state_out[si + 2] = pp;
}

// ---------------- host launcher ----------------
extern "C" void kernel_launch(void* const* d_in, const int* in_sizes, int n_in,
                              void* d_out, int out_size)
{
    const float* x         = (const float*)d_in[0];
    const float* tm_shift  = (const float*)d_in[1];
    const float* wkv_state = (const float*)d_in[2];
    const float* cm_shift  = (const float*)d_in[3];
    const float* ln1_g     = (const float*)d_in[4];
    const float* ln1_b     = (const float*)d_in[5];
    const float* ln2_g     = (const float*)d_in[6];
    const float* ln2_b     = (const float*)d_in[7];
    const float* time_decay= (const float*)d_in[8];
    const float* time_first= (const float*)d_in[9];
    const float* att_mix_k = (const float*)d_in[10];
    const float* att_mix_v = (const float*)d_in[11];
    const float* att_mix_r = (const float*)d_in[12];
    const float* Wk        = (const float*)d_in[13];
    const float* Wv        = (const float*)d_in[14];
    const float* Wr        = (const float*)d_in[15];
    const float* Wo        = (const float*)d_in[16];
    const float* ffn_mix_k = (const float*)d_in[17];
    const float* ffn_mix_r = (const float*)d_in[18];
    const float* Wk_f      = (const float*)d_in[19];
    const float* Wr_f      = (const float*)d_in[20];
    const float* Wv_f      = (const float*)d_in[21];

    float* out     = (float*)d_out;
    float* out_x   = out;
    float* out_wkv = out + BTC;
    float* out_tm  = out_wkv + (size_t)B_ * C_ * 3;
    float* out_cm  = out_tm + (size_t)B_ * C_;

    float *xn, *kb, *vb, *srb, *x1, *xn2, *rb, *kvb;
    __half *ah, *kfb, *wb;
    cudaGetSymbolAddress((void**)&xn,  g_xn);
    cudaGetSymbolAddress((void**)&kb,  g_k);
    cudaGetSymbolAddress((void**)&vb,  g_v);
    cudaGetSymbolAddress((void**)&srb, g_sr);
    cudaGetSymbolAddress((void**)&x1,  g_x1);
    cudaGetSymbolAddress((void**)&xn2, g_xn2);
    cudaGetSymbolAddress((void**)&rb,  g_r);
    cudaGetSymbolAddress((void**)&kvb, g_kv);
    cudaGetSymbolAddress((void**)&ah,  g_ah);
    cudaGetSymbolAddress((void**)&kfb, g_kf);
    cudaGetSymbolAddress((void**)&wb,  g_w);

    cudaFuncSetAttribute(gemm_h<0>, cudaFuncAttributeMaxDynamicSharedMemorySize, GEMM_SMEM);
    cudaFuncSetAttribute(gemm_h<1>, cudaFuncAttributeMaxDynamicSharedMemorySize, GEMM_SMEM);
    cudaFuncSetAttribute(gemm_h<2>, cudaFuncAttributeMaxDynamicSharedMemorySize, GEMM_SMEM);
    cudaFuncSetAttribute(gemm_h<3>, cudaFuncAttributeMaxDynamicSharedMemorySize, GEMM_SMEM);

    const int mixGrid = (int)(BTC / 4 / 256);            // 32768
    const int wCC = (int)((long)A_ * C_ / 4 / 256);      // 4096
    const int wFC = (int)((long)FF_ * C_ / 4 / 256);     // 16384
    const dim3 gA(A_ / BN,  M_ / BM);                    // (16, 128)
    const dim3 gC(C_ / BN,  M_ / BM);                    // (16, 128)
    const dim3 gF(FF_ / BN, M_ / BM);                    // (64, 128)

    // --- attention half ---
    ln_kernel<<<M_, 256>>>(x, ln1_g, ln1_b, xn, out_tm);

    convh_kernel<<<wCC, 256>>>(Wk, wb);
    mix_h_kernel<<<mixGrid, 256>>>(xn, tm_shift, att_mix_k, ah);
    gemm_h<0><<<gA, 256, GEMM_SMEM>>>(C_, A_, ah, wb, nullptr, kb, nullptr);

    convh_kernel<<<wCC, 256>>>(Wv, wb);
    mix_h_kernel<<<mixGrid, 256>>>(xn, tm_shift, att_mix_v, ah);
    gemm_h<0><<<gA, 256, GEMM_SMEM>>>(C_, A_, ah, wb, nullptr, vb, nullptr);

    convh_kernel<<<wCC, 256>>>(Wr, wb);
    mix_h_kernel<<<mixGrid, 256>>>(xn, tm_shift, att_mix_r, ah);
    gemm_h<1><<<gA, 256, GEMM_SMEM>>>(C_, A_, ah, wb, nullptr, srb, nullptr);

    // wkv scan: writes ah = fp16(sr * y) directly
    wkv_kernel<<<(B_ * A_ + 63) / 64, 64>>>(time_decay, time_first,
                                            kb, vb, srb, wkv_state, ah, out_wkv);

    convh_kernel<<<wCC, 256>>>(Wo, wb);
    gemm_h<3><<<gC, 256, GEMM_SMEM>>>(A_, C_, ah, wb, x, x1, nullptr);

    // --- FFN half ---
    ln_kernel<<<M_, 256>>>(x1, ln2_g, ln2_b, xn2, out_cm);

    convh_kernel<<<wFC, 256>>>(Wk_f, wb);
    mix_h_kernel<<<mixGrid, 256>>>(xn2, cm_shift, ffn_mix_k, ah);
    gemm_h<2><<<gF, 256, GEMM_SMEM>>>(C_, FF_, ah, wb, nullptr, nullptr, kfb);

    convh_kernel<<<wCC, 256>>>(Wr_f, wb);
    mix_h_kernel<<<mixGrid, 256>>>(xn2, cm_shift, ffn_mix_r, ah);
    gemm_h<1><<<gC, 256, GEMM_SMEM>>>(C_, C_, ah, wb, nullptr, rb, nullptr);

    convh_kernel<<<wFC, 256>>>(Wv_f, wb);
    gemm_h<0><<<gC, 256, GEMM_SMEM>>>(FF_, C_, kfb, wb, nullptr, kvb, nullptr);

    final_kernel<<<mixGrid, 256>>>(x1, rb, kvb, out_x);
}

// round 11
// speedup vs baseline: 9.6767x; 1.0328x over previous
#include <cuda_runtime.h>
#include <cuda_fp16.h>
#include <math.h>
#include <stdint.h>

constexpr int B_ = 4, T_ = 4096, C_ = 2048, A_ = 2048, FF_ = 8192;
constexpr int M_ = B_ * T_;                   // 16384
constexpr long BTC = (long)B_ * T_ * C_;
constexpr long BTA = (long)B_ * T_ * A_;
constexpr long BTF = (long)B_ * T_ * FF_;

// ---------------- scratch (device globals) ----------------
__device__ float  g_xn [BTC];
__device__ float  g_k  [BTA];
__device__ float  g_v  [BTA];
__device__ float  g_sr [BTA];
__device__ float  g_x1 [BTC];
__device__ float  g_xn2[BTC];
__device__ float  g_r  [BTC];
__device__ __half g_ah [BTC];            // fp16 activation buffer 1
__device__ __half g_ah2[BTC];            // fp16 activation buffer 2
__device__ __half g_ah3[BTC];            // fp16 activation buffer 3
__device__ __half g_kf [BTF];            // fp16 relu^2(kf)
__device__ __half g_w  [(long)FF_ * C_]; // fp16 weight buffer (reused)

// ---------------- PTX helpers ----------------
__device__ __forceinline__ uint32_t smem_u32(const void* p) {
    uint32_t a;
    asm("{ .reg .u64 t; cvta.to.shared.u64 t, %1; cvt.u32.u64 %0, t; }" : "=r"(a) : "l"(p));
    return a;
}
#define CP_ASYNC16(dst, src) \
    asm volatile("cp.async.cg.shared.global [%0], [%1], 16;" :: "r"(dst), "l"(src))
#define CP_COMMIT() asm volatile("cp.async.commit_group;" ::: "memory")
#define CP_WAIT1()  asm volatile("cp.async.wait_group 1;"  ::: "memory")

#define LDSM_X4(r0, r1, r2, r3, addr) \
    asm volatile("ldmatrix.sync.aligned.m8n8.x4.shared.b16 {%0,%1,%2,%3}, [%4];" \
                 : "=r"(r0), "=r"(r1), "=r"(r2), "=r"(r3) : "r"(addr))

#define MMA16816(c, a, b0, b1) \
    asm volatile("mma.sync.aligned.m16n8k16.row.col.f32.f16.f16.f32 " \
                 "{%0,%1,%2,%3}, {%4,%5,%6,%7}, {%8,%9}, {%0,%1,%2,%3};" \
                 : "+f"((c)[0]), "+f"((c)[1]), "+f"((c)[2]), "+f"((c)[3]) \
                 : "r"((a)[0]), "r"((a)[1]), "r"((a)[2]), "r"((a)[3]), \
                   "r"(b0), "r"(b1))

// ---------------- fp16 tensor-core GEMM ----------------
// out[m,n] = sum_k A[m,k] * W[n,k]; A,W fp16 row-major (k contiguous), acc fp32.
// CTA tile 128x128, BK=64, 3-stage cp.async, 8 warps (4m x 2n), warp tile 32x64.
// 2 CTAs / SM (96KB smem each) to cover sync/LDSM bubbles.
constexpr int BM = 128, BN = 128, BK = 64, STAGES = 3;
constexpr uint32_t STAGE_BYTES = 32768;              // A 16KB + B 16KB
constexpr uint32_t GEMM_SMEM = STAGES * STAGE_BYTES; // 98304

__device__ __forceinline__ void load_stage(
    uint32_t st, const __half* Ab, const __half* Wb, int K, int k0, int tid)
{
    #pragma unroll
    for (int j = 0; j < 4; j++) {
        int q = tid + j * 256;
        int r = q >> 3, c = q & 7;
        CP_ASYNC16(st + r * 128 + ((c ^ (r & 7)) << 4),
                   Ab + (size_t)r * K + k0 + c * 8);
    }
    #pragma unroll
    for (int j = 0; j < 4; j++) {
        int q = tid + j * 256;
        int r = q >> 3, c = q & 7;
        CP_ASYNC16(st + 16384 + r * 128 + ((c ^ (r & 7)) << 4),
                   Wb + (size_t)r * K + k0 + c * 8);
    }
}

// EPI: 0 = fp32 out, 1 = sigmoid fp32, 2 = relu^2 -> fp16,
//      3 = +residual fp32, 4 = Res + Rmul*acc fp32 (fused final)
template <int EPI>
__global__ __launch_bounds__(256, 2)
void gemm_h(int K, int N,
            const __half* __restrict__ A, const __half* __restrict__ W,
            const float* __restrict__ Res, const float* __restrict__ Rmul,
            float* __restrict__ Out, __half* __restrict__ OutH)
{
    extern __shared__ char smem_raw[];
    const uint32_t sbase = smem_u32(smem_raw);
    const int tid = threadIdx.x;
    const int wid = tid >> 5;
    const int lane = tid & 31;
    const int wm = wid >> 1;      // 0..3
    const int wn = wid & 1;       // 0..1

    const __half* Ab = A + (size_t)blockIdx.y * BM * K;
    const __half* Wb = W + (size_t)blockIdx.x * BN * K;

    float acc[2][8][4];
    #pragma unroll
    for (int i = 0; i < 2; i++)
        #pragma unroll
        for (int j = 0; j < 8; j++)
            #pragma unroll
            for (int q = 0; q < 4; q++) acc[i][j][q] = 0.f;

    // lane-constant address components
    const int laA = lane & 15;            // A row offset
    const int caA = lane >> 4;            // A chunk offset (k-half)
    const int laB = (lane & 7) + ((lane & 16) >> 1);  // B row offset
    const int caB = (lane >> 3) & 1;      // B chunk offset
    const int rA = wm * 32 + laA;         // +mi*16
    const int rB = wn * 64 + laB;         // +16*j

    const int NT = K / BK;
    #pragma unroll 1
    for (int s = 0; s < STAGES - 1; s++) {
        load_stage(sbase + s * STAGE_BYTES, Ab, Wb, K, s * BK, tid);
        CP_COMMIT();
    }

    #pragma unroll 1
    for (int i = 0; i < NT; i++) {
        CP_WAIT1();
        __syncthreads();

        if (i + STAGES - 1 < NT)
            load_stage(sbase + ((i + STAGES - 1) % STAGES) * STAGE_BYTES,
                       Ab, Wb, K, (i + STAGES - 1) * BK, tid);
        CP_COMMIT();

        const uint32_t As = sbase + (i % STAGES) * STAGE_BYTES;
        const uint32_t Bs = As + 16384;

        #pragma unroll
        for (int kk = 0; kk < 4; kk++) {
            uint32_t a[2][4];
            #pragma unroll
            for (int mi = 0; mi < 2; mi++) {
                const int r = rA + mi * 16;
                const int c = 2 * kk + caA;
                LDSM_X4(a[mi][0], a[mi][1], a[mi][2], a[mi][3],
                        As + r * 128 + ((c ^ (r & 7)) << 4));
            }
            uint32_t b[8][2];
            #pragma unroll
            for (int j = 0; j < 4; j++) {
                const int r = rB + 16 * j;
                const int c = 2 * kk + caB;
                LDSM_X4(b[2*j][0], b[2*j][1], b[2*j+1][0], b[2*j+1][1],
                        Bs + r * 128 + ((c ^ (r & 7)) << 4));
            }
            #pragma unroll
            for (int mi = 0; mi < 2; mi++)
                #pragma unroll
                for (int j = 0; j < 8; j++)
                    MMA16816(acc[mi][j], a[mi], b[j][0], b[j][1]);
        }
    }

    // ---- epilogue ----
    const int g   = lane >> 2;
    const int tig = lane & 3;
    const size_t row0 = (size_t)blockIdx.y * BM + wm * 32;
    const size_t col0 = (size_t)blockIdx.x * BN + wn * 64;

    #pragma unroll
    for (int mi = 0; mi < 2; mi++) {
        #pragma unroll
        for (int h = 0; h < 2; h++) {
            const size_t r = row0 + mi * 16 + h * 8 + g;
            #pragma unroll
            for (int j = 0; j < 8; j++) {
                const size_t c = col0 + j * 8 + 2 * tig;
                float vx = acc[mi][j][2 * h];
                float vy = acc[mi][j][2 * h + 1];
                if (EPI == 1) {
                    vx = 1.f / (1.f + __expf(-vx));
                    vy = 1.f / (1.f + __expf(-vy));
                } else if (EPI == 3) {
                    const float2 rr = *(const float2*)(Res + r * N + c);
                    vx += rr.x; vy += rr.y;
                } else if (EPI == 4) {
                    const float2 rr = *(const float2*)(Res + r * N + c);
                    const float2 rm = *(const float2*)(Rmul + r * N + c);
                    vx = rr.x + rm.x * vx;
                    vy = rr.y + rm.y * vy;
                }
                if (EPI == 2) {
                    vx = fmaxf(vx, 0.f); vx *= vx;
                    vy = fmaxf(vy, 0.f); vy *= vy;
                    *(__half2*)(OutH + r * N + c) = __floats2half2_rn(vx, vy);
                } else {
                    *(float2*)(Out + r * N + c) = make_float2(vx, vy);
                }
            }
        }
    }
}

// ---------------- elementwise kernels ----------------
__global__ __launch_bounds__(256)
void ln_kernel(const float* __restrict__ x, const float* __restrict__ g,
               const float* __restrict__ b, float* __restrict__ out,
               float* __restrict__ shift_out)
{
    const int row = blockIdx.x;
    const float4* xr = (const float4*)(x + (size_t)row * C_);
    const int tid = threadIdx.x;

    float4 v0 = xr[tid];
    float4 v1 = xr[tid + 256];

    float s  = v0.x + v0.y + v0.z + v0.w + v1.x + v1.y + v1.z + v1.w;
    float sq = v0.x*v0.x + v0.y*v0.y + v0.z*v0.z + v0.w*v0.w
             + v1.x*v1.x + v1.y*v1.y + v1.z*v1.z + v1.w*v1.w;

    #pragma unroll
    for (int o = 16; o > 0; o >>= 1) {
        s  += __shfl_xor_sync(0xFFFFFFFFu, s,  o);
        sq += __shfl_xor_sync(0xFFFFFFFFu, sq, o);
    }
    __shared__ float ss[8], sqs[8];
    if ((tid & 31) == 0) { ss[tid >> 5] = s; sqs[tid >> 5] = sq; }
    __syncthreads();
    float ts = 0.f, tsq = 0.f;
    #pragma unroll
    for (int i = 0; i < 8; i++) { ts += ss[i]; tsq += sqs[i]; }

    const float mean = ts * (1.0f / C_);
    const float var  = tsq * (1.0f / C_) - mean * mean;
    const float rstd = rsqrtf(var + 1e-5f);

    const float4* g4 = (const float4*)g;
    const float4* b4 = (const float4*)b;
    float4 gg0 = g4[tid],       bb0 = b4[tid];
    float4 gg1 = g4[tid + 256], bb1 = b4[tid + 256];

    float4 o0, o1;
    o0.x = (v0.x - mean) * rstd * gg0.x + bb0.x;
    o0.y = (v0.y - mean) * rstd * gg0.y + bb0.y;
    o0.z = (v0.z - mean) * rstd * gg0.z + bb0.z;
    o0.w = (v0.w - mean) * rstd * gg0.w + bb0.w;
    o1.x = (v1.x - mean) * rstd * gg1.x + bb1.x;
    o1.y = (v1.y - mean) * rstd * gg1.y + bb1.y;
    o1.z = (v1.z - mean) * rstd * gg1.z + bb1.z;
    o1.w = (v1.w - mean) * rstd * gg1.w + bb1.w;

    float4* orow = (float4*)(out + (size_t)row * C_);
    orow[tid]       = o0;
    orow[tid + 256] = o1;

    if (shift_out != nullptr && (row % T_) == (T_ - 1)) {
        float4* sp2 = (float4*)(shift_out + (size_t)(row / T_) * C_);
        sp2[tid]       = o0;
        sp2[tid + 256] = o1;
    }
}

__device__ __forceinline__ void mix_one(float4 cur, float4 prev, float4 m,
                                        __half* out, long i4)
{
    float4 o;
    o.x = cur.x * m.x + prev.x * (1.f - m.x);
    o.y = cur.y * m.y + prev.y * (1.f - m.y);
    o.z = cur.z * m.z + prev.z * (1.f - m.z);
    o.w = cur.w * m.w + prev.w * (1.f - m.w);
    __half2* op = (__half2*)out + i4 * 2;
    op[0] = __floats2half2_rn(o.x, o.y);
    op[1] = __floats2half2_rn(o.z, o.w);
}

// fused 3-way mix (attention): one read of xn, three fp16 outputs
__global__ __launch_bounds__(256)
void mix3_h_kernel(const float* __restrict__ xn, const float* __restrict__ shift,
                   const float* __restrict__ mk, const float* __restrict__ mv,
                   const float* __restrict__ mr,
                   __half* __restrict__ ok, __half* __restrict__ ov,
                   __half* __restrict__ orr)
{
    const long i4 = (long)blockIdx.x * 256 + threadIdx.x;
    const long e  = i4 * 4;
    const int  c4 = (int)((e % C_) >> 2);
    const long row = e / C_;
    const int  t  = (int)(row % T_);
    const int  bb = (int)(row / T_);

    float4 cur = ((const float4*)xn)[i4];
    float4 prev = (t == 0) ? ((const float4*)shift)[(long)bb * (C_ / 4) + c4]
                           : ((const float4*)xn)[i4 - C_ / 4];
    mix_one(cur, prev, ((const float4*)mk)[c4], ok,  i4);
    mix_one(cur, prev, ((const float4*)mv)[c4], ov,  i4);
    mix_one(cur, prev, ((const float4*)mr)[c4], orr, i4);
}

// fused 2-way mix (FFN)
__global__ __launch_bounds__(256)
void mix2_h_kernel(const float* __restrict__ xn, const float* __restrict__ shift,
                   const float* __restrict__ mk, const float* __restrict__ mr,
                   __half* __restrict__ ok, __half* __restrict__ orr)
{
    const long i4 = (long)blockIdx.x * 256 + threadIdx.x;
    const long e  = i4 * 4;
    const int  c4 = (int)((e % C_) >> 2);
    const long row = e / C_;
    const int  t  = (int)(row % T_);
    const int  bb = (int)(row / T_);

    float4 cur = ((const float4*)xn)[i4];
    float4 prev = (t == 0) ? ((const float4*)shift)[(long)bb * (C_ / 4) + c4]
                           : ((const float4*)xn)[i4 - C_ / 4];
    mix_one(cur, prev, ((const float4*)mk)[c4], ok,  i4);
    mix_one(cur, prev, ((const float4*)mr)[c4], orr, i4);
}

// fp32 -> fp16
__global__ __launch_bounds__(256)
void convh_kernel(const float* __restrict__ in, __half* __restrict__ out)
{
    const long i4 = (long)blockIdx.x * 256 + threadIdx.x;
    float4 v = ((const float4*)in)[i4];
    __half2* op = (__half2*)out + i4 * 2;
    op[0] = __floats2half2_rn(v.x, v.y);
    op[1] = __floats2half2_rn(v.z, v.w);
}

// ---------------- WKV scan (software-pipelined, fuses sr*y -> fp16) ----------
constexpr int WU = 8;   // unroll / prefetch group
__global__ __launch_bounds__(64)
void wkv_kernel(const float* __restrict__ td, const float* __restrict__ tf,
                const float* __restrict__ k, const float* __restrict__ v,
                const float* __restrict__ sr, const float* __restrict__ state_in,
                __half* __restrict__ ah, float* __restrict__ state_out)
{
    const int gid = blockIdx.x * 64 + threadIdx.x;
    if (gid >= B_ * A_) return;
    const int b = gid / A_;
    const int a = gid % A_;

    const float w = -__expf(td[a]);
    const float u = tf[a];

    const size_t base = (size_t)b * T_ * A_ + a;
    const float* kp = k + base;
    const float* vp = v + base;
    const float* sp = sr + base;
    __half*      yp = ah + base;

    const size_t si = ((size_t)b * A_ + a) * 3;
    float aa = state_in[si + 0];
    float bb = state_in[si + 1];
    float pp = state_in[si + 2];

    float ka[WU], va[WU], sa[WU];
    float kn[WU], vn[WU], sn[WU];
    #pragma unroll
    for (int j = 0; j < WU; j++) {
        ka[j] = kp[(size_t)j * A_];
        va[j] = vp[(size_t)j * A_];
        sa[j] = sp[(size_t)j * A_];
    }

    constexpr int NG = T_ / WU;
    #pragma unroll 1
    for (int g = 0; g < NG; g++) {
        if (g + 1 < NG) {
            const size_t o = (size_t)(g + 1) * WU * A_;
            #pragma unroll
            for (int j = 0; j < WU; j++) {
                kn[j] = kp[o + (size_t)j * A_];
                vn[j] = vp[o + (size_t)j * A_];
                sn[j] = sp[o + (size_t)j * A_];
            }
        }
        const size_t yo = (size_t)g * WU * A_;
        #pragma unroll
        for (int j = 0; j < WU; j++) {
            const float kt = ka[j];
            const float vt = va[j];

            float ww = u + kt;
            float p  = fmaxf(pp, ww);
            float e1 = __expf(pp - p);
            float e2 = __expf(ww - p);
            const float y = (e1 * aa + e2 * vt) / (e1 * bb + e2);
            yp[yo + (size_t)j * A_] = __float2half(sa[j] * y);

            ww = pp + w;
            p  = fmaxf(ww, kt);
            e1 = __expf(ww - p);
            e2 = __expf(kt - p);
            aa = e1 * aa + e2 * vt;
            bb = e1 * bb + e2;
            pp = p;
        }
        #pragma unroll
        for (int j = 0; j < WU; j++) { ka[j] = kn[j]; va[j] = vn[j]; sa[j] = sn[j]; }
    }
    state_out[si + 0] = aa;
    state_out[si + 1] = bb;
    state_out[si + 2] = pp;
}

// ---------------- host launcher ----------------
extern "C" void kernel_launch(void* const* d_in, const int* in_sizes, int n_in,
                              void* d_out, int out_size)
{
    const float* x         = (const float*)d_in[0];
    const float* tm_shift  = (const float*)d_in[1];
    const float* wkv_state = (const float*)d_in[2];
    const float* cm_shift  = (const float*)d_in[3];
    const float* ln1_g     = (const float*)d_in[4];
    const float* ln1_b     = (const float*)d_in[5];
    const float* ln2_g     = (const float*)d_in[6];
    const float* ln2_b     = (const float*)d_in[7];
    const float* time_decay= (const float*)d_in[8];
    const float* time_first= (const float*)d_in[9];
    const float* att_mix_k = (const float*)d_in[10];
    const float* att_mix_v = (const float*)d_in[11];
    const float* att_mix_r = (const float*)d_in[12];
    const float* Wk        = (const float*)d_in[13];
    const float* Wv        = (const float*)d_in[14];
    const float* Wr        = (const float*)d_in[15];
    const float* Wo        = (const float*)d_in[16];
    const float* ffn_mix_k = (const float*)d_in[17];
    const float* ffn_mix_r = (const float*)d_in[18];
    const float* Wk_f      = (const float*)d_in[19];
    const float* Wr_f      = (const float*)d_in[20];
    const float* Wv_f      = (const float*)d_in[21];

    float* out     = (float*)d_out;
    float* out_x   = out;
    float* out_wkv = out + BTC;
    float* out_tm  = out_wkv + (size_t)B_ * C_ * 3;
    float* out_cm  = out_tm + (size_t)B_ * C_;

    float *xn, *kb, *vb, *srb, *x1, *xn2, *rb;
    __half *ah, *ah2, *ah3, *kfb, *wb;
    cudaGetSymbolAddress((void**)&xn,  g_xn);
    cudaGetSymbolAddress((void**)&kb,  g_k);
    cudaGetSymbolAddress((void**)&vb,  g_v);
    cudaGetSymbolAddress((void**)&srb, g_sr);
    cudaGetSymbolAddress((void**)&x1,  g_x1);
    cudaGetSymbolAddress((void**)&xn2, g_xn2);
    cudaGetSymbolAddress((void**)&rb,  g_r);
    cudaGetSymbolAddress((void**)&ah,  g_ah);
    cudaGetSymbolAddress((void**)&ah2, g_ah2);
    cudaGetSymbolAddress((void**)&ah3, g_ah3);
    cudaGetSymbolAddress((void**)&kfb, g_kf);
    cudaGetSymbolAddress((void**)&wb,  g_w);

    cudaFuncSetAttribute(gemm_h<0>, cudaFuncAttributeMaxDynamicSharedMemorySize, GEMM_SMEM);
    cudaFuncSetAttribute(gemm_h<1>, cudaFuncAttributeMaxDynamicSharedMemorySize, GEMM_SMEM);
    cudaFuncSetAttribute(gemm_h<2>, cudaFuncAttributeMaxDynamicSharedMemorySize, GEMM_SMEM);
    cudaFuncSetAttribute(gemm_h<3>, cudaFuncAttributeMaxDynamicSharedMemorySize, GEMM_SMEM);
    cudaFuncSetAttribute(gemm_h<4>, cudaFuncAttributeMaxDynamicSharedMemorySize, GEMM_SMEM);

    const int mixGrid = (int)(BTC / 4 / 256);            // 32768
    const int wCC = (int)((long)A_ * C_ / 4 / 256);      // 4096
    const int wFC = (int)((long)FF_ * C_ / 4 / 256);     // 16384
    const dim3 gA(A_ / BN,  M_ / BM);                    // (16, 128)
    const dim3 gC(C_ / BN,  M_ / BM);                    // (16, 128)
    const dim3 gF(FF_ / BN, M_ / BM);                    // (64, 128)

    // --- attention half ---
    ln_kernel<<<M_, 256>>>(x, ln1_g, ln1_b, xn, out_tm);

    mix3_h_kernel<<<mixGrid, 256>>>(xn, tm_shift, att_mix_k, att_mix_v, att_mix_r,
                                    ah, ah2, ah3);

    convh_kernel<<<wCC, 256>>>(Wk, wb);
    gemm_h<0><<<gA, 256, GEMM_SMEM>>>(C_, A_, ah, wb, nullptr, nullptr, kb, nullptr);

    convh_kernel<<<wCC, 256>>>(Wv, wb);
    gemm_h<0><<<gA, 256, GEMM_SMEM>>>(C_, A_, ah2, wb, nullptr, nullptr, vb, nullptr);

    convh_kernel<<<wCC, 256>>>(Wr, wb);
    gemm_h<1><<<gA, 256, GEMM_SMEM>>>(C_, A_, ah3, wb, nullptr, nullptr, srb, nullptr);

    // wkv scan: writes ah = fp16(sr * y) directly
    wkv_kernel<<<(B_ * A_ + 63) / 64, 64>>>(time_decay, time_first,
                                            kb, vb, srb, wkv_state, ah, out_wkv);

    convh_kernel<<<wCC, 256>>>(Wo, wb);
    gemm_h<3><<<gC, 256, GEMM_SMEM>>>(A_, C_, ah, wb, x, nullptr, x1, nullptr);

    // --- FFN half ---
    ln_kernel<<<M_, 256>>>(x1, ln2_g, ln2_b, xn2, out_cm);

    mix2_h_kernel<<<mixGrid, 256>>>(xn2, cm_shift, ffn_mix_k, ffn_mix_r, ah, ah2);

    convh_kernel<<<wFC, 256>>>(Wk_f, wb);
    gemm_h<2><<<gF, 256, GEMM_SMEM>>>(C_, FF_, ah, wb, nullptr, nullptr, nullptr, kfb);

    convh_kernel<<<wCC, 256>>>(Wr_f, wb);
    gemm_h<1><<<gC, 256, GEMM_SMEM>>>(C_, C_, ah2, wb, nullptr, nullptr, rb, nullptr);

    convh_kernel<<<wFC, 256>>>(Wv_f, wb);
    // fused final: out = x1 + rb * (kf @ Wv_f^T)
    gemm_h<4><<<gC, 256, GEMM_SMEM>>>(FF_, C_, kfb, wb, x1, rb, out_x, nullptr);
}

// round 16
// speedup vs baseline: 9.7487x; 1.0074x over previous
#include <cuda_runtime.h>
#include <cuda_fp16.h>
#include <math.h>
#include <stdint.h>

constexpr int B_ = 4, T_ = 4096, C_ = 2048, A_ = 2048, FF_ = 8192;
constexpr int M_ = B_ * T_;                   // 16384
constexpr long BTC = (long)B_ * T_ * C_;
constexpr long BTA = (long)B_ * T_ * A_;
constexpr long BTF = (long)B_ * T_ * FF_;

// ---------------- scratch (device globals) ----------------
__device__ float  g_k  [BTA];
__device__ float  g_v  [BTA];
__device__ float  g_sr [BTA];
__device__ float  g_x1 [BTC];
__device__ float  g_r  [BTC];
__device__ __half g_ah [BTC];            // fp16 activation buffer 1
__device__ __half g_ah2[BTC];            // fp16 activation buffer 2
__device__ __half g_ah3[BTC];            // fp16 activation buffer 3
__device__ __half g_kf [BTF];            // fp16 relu^2(kf)
__device__ __half g_w  [(long)FF_ * C_]; // fp16 weight buffer (reused)

// ---------------- PTX helpers ----------------
__device__ __forceinline__ uint32_t smem_u32(const void* p) {
    uint32_t a;
    asm("{ .reg .u64 t; cvta.to.shared.u64 t, %1; cvt.u32.u64 %0, t; }" : "=r"(a) : "l"(p));
    return a;
}
#define CP_ASYNC16(dst, src) \
    asm volatile("cp.async.cg.shared.global [%0], [%1], 16;" :: "r"(dst), "l"(src))
#define CP_COMMIT() asm volatile("cp.async.commit_group;" ::: "memory")
#define CP_WAIT1()  asm volatile("cp.async.wait_group 1;"  ::: "memory")

#define LDSM_X4(r0, r1, r2, r3, addr) \
    asm volatile("ldmatrix.sync.aligned.m8n8.x4.shared.b16 {%0,%1,%2,%3}, [%4];" \
                 : "=r"(r0), "=r"(r1), "=r"(r2), "=r"(r3) : "r"(addr))

#define MMA16816(c, a, b0, b1) \
    asm volatile("mma.sync.aligned.m16n8k16.row.col.f32.f16.f16.f32 " \
                 "{%0,%1,%2,%3}, {%4,%5,%6,%7}, {%8,%9}, {%0,%1,%2,%3};" \
                 : "+f"((c)[0]), "+f"((c)[1]), "+f"((c)[2]), "+f"((c)[3]) \
                 : "r"((a)[0]), "r"((a)[1]), "r"((a)[2]), "r"((a)[3]), \
                   "r"(b0), "r"(b1))

// ---------------- fp16 tensor-core GEMM (unchanged from R5/R6) ----------------
constexpr int BM = 128, BN = 128, BK = 64, STAGES = 3;
constexpr uint32_t STAGE_BYTES = 32768;              // A 16KB + B 16KB
constexpr uint32_t GEMM_SMEM = STAGES * STAGE_BYTES; // 98304

__device__ __forceinline__ void load_stage(
    uint32_t st, const __half* Ab, const __half* Wb, int K, int k0, int tid)
{
    #pragma unroll
    for (int j = 0; j < 4; j++) {
        int q = tid + j * 256;
        int r = q >> 3, c = q & 7;
        CP_ASYNC16(st + r * 128 + ((c ^ (r & 7)) << 4),
                   Ab + (size_t)r * K + k0 + c * 8);
    }
    #pragma unroll
    for (int j = 0; j < 4; j++) {
        int q = tid + j * 256;
        int r = q >> 3, c = q & 7;
        CP_ASYNC16(st + 16384 + r * 128 + ((c ^ (r & 7)) << 4),
                   Wb + (size_t)r * K + k0 + c * 8);
    }
}

// EPI: 0 = fp32 out, 1 = sigmoid fp32, 2 = relu^2 -> fp16,
//      3 = +residual fp32, 4 = Res + Rmul*acc fp32 (fused final)
template <int EPI>
__global__ __launch_bounds__(256, 2)
void gemm_h(int K, int N,
            const __half* __restrict__ A, const __half* __restrict__ W,
            const float* __restrict__ Res, const float* __restrict__ Rmul,
            float* __restrict__ Out, __half* __restrict__ OutH)
{
    extern __shared__ char smem_raw[];
    const uint32_t sbase = smem_u32(smem_raw);
    const int tid = threadIdx.x;
    const int wid = tid >> 5;
    const int lane = tid & 31;
    const int wm = wid >> 1;      // 0..3
    const int wn = wid & 1;       // 0..1

    const __half* Ab = A + (size_t)blockIdx.y * BM * K;
    const __half* Wb = W + (size_t)blockIdx.x * BN * K;

    float acc[2][8][4];
    #pragma unroll
    for (int i = 0; i < 2; i++)
        #pragma unroll
        for (int j = 0; j < 8; j++)
            #pragma unroll
            for (int q = 0; q < 4; q++) acc[i][j][q] = 0.f;

    const int laA = lane & 15;
    const int caA = lane >> 4;
    const int laB = (lane & 7) + ((lane & 16) >> 1);
    const int caB = (lane >> 3) & 1;
    const int rA = wm * 32 + laA;
    const int rB = wn * 64 + laB;

    const int NT = K / BK;
    #pragma unroll 1
    for (int s = 0; s < STAGES - 1; s++) {
        load_stage(sbase + s * STAGE_BYTES, Ab, Wb, K, s * BK, tid);
        CP_COMMIT();
    }

    #pragma unroll 1
    for (int i = 0; i < NT; i++) {
        CP_WAIT1();
        __syncthreads();

        if (i + STAGES - 1 < NT)
            load_stage(sbase + ((i + STAGES - 1) % STAGES) * STAGE_BYTES,
                       Ab, Wb, K, (i + STAGES - 1) * BK, tid);
        CP_COMMIT();

        const uint32_t As = sbase + (i % STAGES) * STAGE_BYTES;
        const uint32_t Bs = As + 16384;

        #pragma unroll
        for (int kk = 0; kk < 4; kk++) {
            uint32_t a[2][4];
            #pragma unroll
            for (int mi = 0; mi < 2; mi++) {
                const int r = rA + mi * 16;
                const int c = 2 * kk + caA;
                LDSM_X4(a[mi][0], a[mi][1], a[mi][2], a[mi][3],
                        As + r * 128 + ((c ^ (r & 7)) << 4));
            }
            uint32_t b[8][2];
            #pragma unroll
            for (int j = 0; j < 4; j++) {
                const int r = rB + 16 * j;
                const int c = 2 * kk + caB;
                LDSM_X4(b[2*j][0], b[2*j][1], b[2*j+1][0], b[2*j+1][1],
                        Bs + r * 128 + ((c ^ (r & 7)) << 4));
            }
            #pragma unroll
            for (int mi = 0; mi < 2; mi++)
                #pragma unroll
                for (int j = 0; j < 8; j++)
                    MMA16816(acc[mi][j], a[mi], b[j][0], b[j][1]);
        }
    }

    // ---- epilogue ----
    const int g   = lane >> 2;
    const int tig = lane & 3;
    const size_t row0 = (size_t)blockIdx.y * BM + wm * 32;
    const size_t col0 = (size_t)blockIdx.x * BN + wn * 64;

    #pragma unroll
    for (int mi = 0; mi < 2; mi++) {
        #pragma unroll
        for (int h = 0; h < 2; h++) {
            const size_t r = row0 + mi * 16 + h * 8 + g;
            #pragma unroll
            for (int j = 0; j < 8; j++) {
                const size_t c = col0 + j * 8 + 2 * tig;
                float vx = acc[mi][j][2 * h];
                float vy = acc[mi][j][2 * h + 1];
                if (EPI == 1) {
                    vx = 1.f / (1.f + __expf(-vx));
                    vy = 1.f / (1.f + __expf(-vy));
                } else if (EPI == 3) {
                    const float2 rr = *(const float2*)(Res + r * N + c);
                    vx += rr.x; vy += rr.y;
                } else if (EPI == 4) {
                    const float2 rr = *(const float2*)(Res + r * N + c);
                    const float2 rm = *(const float2*)(Rmul + r * N + c);
                    vx = rr.x + rm.x * vx;
                    vy = rr.y + rm.y * vy;
                }
                if (EPI == 2) {
                    vx = fmaxf(vx, 0.f); vx *= vx;
                    vy = fmaxf(vy, 0.f); vy *= vy;
                    *(__half2*)(OutH + r * N + c) = __floats2half2_rn(vx, vy);
                } else {
                    *(float2*)(Out + r * N + c) = make_float2(vx, vy);
                }
            }
        }
    }
}

// ---------------- fused LayerNorm + mix kernels ----------------
// One block per row t. Computes LN stats for row t AND row t-1 (recompute),
// emits fp16 mixed activations directly. prev source at t==0 is the RAW shift
// input (matches reference: xx = concat(shift, xn[:-1])).
// NMIX = 3 (attention: k,v,r) or 2 (FFN: k,r).

__device__ __forceinline__ void row_stats(float4 v0, float4 v1,
                                          float& mean, float& rstd, int tid)
{
    float s  = v0.x + v0.y + v0.z + v0.w + v1.x + v1.y + v1.z + v1.w;
    float sq = v0.x*v0.x + v0.y*v0.y + v0.z*v0.z + v0.w*v0.w
             + v1.x*v1.x + v1.y*v1.y + v1.z*v1.z + v1.w*v1.w;
    #pragma unroll
    for (int o = 16; o > 0; o >>= 1) {
        s  += __shfl_xor_sync(0xFFFFFFFFu, s,  o);
        sq += __shfl_xor_sync(0xFFFFFFFFu, sq, o);
    }
    __shared__ float ss[8], sqs[8];
    if ((tid & 31) == 0) { ss[tid >> 5] = s; sqs[tid >> 5] = sq; }
    __syncthreads();
    float ts = 0.f, tsq = 0.f;
    #pragma unroll
    for (int i = 0; i < 8; i++) { ts += ss[i]; tsq += sqs[i]; }
    mean = ts * (1.0f / C_);
    const float var = tsq * (1.0f / C_) - mean * mean;
    rstd = rsqrtf(var + 1e-5f);
}

__device__ __forceinline__ float4 ln4(float4 v, float mean, float rstd,
                                      float4 gg, float4 bb)
{
    float4 o;
    o.x = (v.x - mean) * rstd * gg.x + bb.x;
    o.y = (v.y - mean) * rstd * gg.y + bb.y;
    o.z = (v.z - mean) * rstd * gg.z + bb.z;
    o.w = (v.w - mean) * rstd * gg.w + bb.w;
    return o;
}

__device__ __forceinline__ void mix_emit(float4 cur, float4 prev, float4 m,
                                         __half* out, size_t i4)
{
    float4 o;
    o.x = cur.x * m.x + prev.x * (1.f - m.x);
    o.y = cur.y * m.y + prev.y * (1.f - m.y);
    o.z = cur.z * m.z + prev.z * (1.f - m.z);
    o.w = cur.w * m.w + prev.w * (1.f - m.w);
    __half2* op = (__half2*)out + i4 * 2;
    op[0] = __floats2half2_rn(o.x, o.y);
    op[1] = __floats2half2_rn(o.z, o.w);
}

template <int NMIX>
__global__ __launch_bounds__(256)
void ln_mix_kernel(const float* __restrict__ x, const float* __restrict__ shift,
                   const float* __restrict__ g, const float* __restrict__ b,
                   const float* __restrict__ m0, const float* __restrict__ m1,
                   const float* __restrict__ m2,
                   __half* __restrict__ o0, __half* __restrict__ o1,
                   __half* __restrict__ o2,
                   float* __restrict__ shift_out)
{
    const int row = blockIdx.x;                    // b*T + t
    const int t   = row % T_;
    const int bb_ = row / T_;
    const int tid = threadIdx.x;

    const float4* xr = (const float4*)(x + (size_t)row * C_);
    float4 c0 = xr[tid];
    float4 c1 = xr[tid + 256];

    float meanC, rstdC;
    row_stats(c0, c1, meanC, rstdC, tid);

    const float4* g4 = (const float4*)g;
    const float4* b4 = (const float4*)b;
    float4 gg0 = g4[tid],       bb0 = b4[tid];
    float4 gg1 = g4[tid + 256], bb1 = b4[tid + 256];

    float4 xc0 = ln4(c0, meanC, rstdC, gg0, bb0);
    float4 xc1 = ln4(c1, meanC, rstdC, gg1, bb1);

    float4 xp0, xp1;
    if (t == 0) {
        const float4* sp = (const float4*)(shift + (size_t)bb_ * C_);
        xp0 = sp[tid];
        xp1 = sp[tid + 256];
    } else {
        const float4* pr = (const float4*)(x + (size_t)(row - 1) * C_);
        float4 p0 = pr[tid];
        float4 p1 = pr[tid + 256];
        __syncthreads();   // reuse of ss/sqs in row_stats
        float meanP, rstdP;
        row_stats(p0, p1, meanP, rstdP, tid);
        xp0 = ln4(p0, meanP, rstdP, gg0, bb0);
        xp1 = ln4(p1, meanP, rstdP, gg1, bb1);
    }

    const size_t i4a = (size_t)row * (C_ / 4) + tid;
    const size_t i4b = i4a + 256;
    const float4* m0p = (const float4*)m0;
    mix_emit(xc0, xp0, m0p[tid],       o0, i4a);
    mix_emit(xc1, xp1, m0p[tid + 256], o0, i4b);
    const float4* m1p = (const float4*)m1;
    mix_emit(xc0, xp0, m1p[tid],       o1, i4a);
    mix_emit(xc1, xp1, m1p[tid + 256], o1, i4b);
    if (NMIX == 3) {
        const float4* m2p = (const float4*)m2;
        mix_emit(xc0, xp0, m2p[tid],       o2, i4a);
        mix_emit(xc1, xp1, m2p[tid + 256], o2, i4b);
    }

    if (t == T_ - 1) {
        float4* so = (float4*)(shift_out + (size_t)bb_ * C_);
        so[tid]       = xc0;
        so[tid + 256] = xc1;
    }
}

// fp32 -> fp16
__global__ __launch_bounds__(256)
void convh_kernel(const float* __restrict__ in, __half* __restrict__ out)
{
    const long i4 = (long)blockIdx.x * 256 + threadIdx.x;
    float4 v = ((const float4*)in)[i4];
    __half2* op = (__half2*)out + i4 * 2;
    op[0] = __floats2half2_rn(v.x, v.y);
    op[1] = __floats2half2_rn(v.z, v.w);
}

// ---------------- WKV scan (software-pipelined, fuses sr*y -> fp16) ----------
constexpr int WU = 8;
__global__ __launch_bounds__(64)
void wkv_kernel(const float* __restrict__ td, const float* __restrict__ tf,
                const float* __restrict__ k, const float* __restrict__ v,
                const float* __restrict__ sr, const float* __restrict__ state_in,
                __half* __restrict__ ah, float* __restrict__ state_out)
{
    const int gid = blockIdx.x * 64 + threadIdx.x;
    if (gid >= B_ * A_) return;
    const int b = gid / A_;
    const int a = gid % A_;

    const float w = -__expf(td[a]);
    const float u = tf[a];

    const size_t base = (size_t)b * T_ * A_ + a;
    const float* kp = k + base;
    const float* vp = v + base;
    const float* sp = sr + base;
    __half*      yp = ah + base;

    const size_t si = ((size_t)b * A_ + a) * 3;
    float aa = state_in[si + 0];
    float bb = state_in[si + 1];
    float pp = state_in[si + 2];

    float ka[WU], va[WU], sa[WU];
    float kn[WU], vn[WU], sn[WU];
    #pragma unroll
    for (int j = 0; j < WU; j++) {
        ka[j] = kp[(size_t)j * A_];
        va[j] = vp[(size_t)j * A_];
        sa[j] = sp[(size_t)j * A_];
    }

    constexpr int NG = T_ / WU;
    #pragma unroll 1
    for (int g = 0; g < NG; g++) {
        if (g + 1 < NG) {
            const size_t o = (size_t)(g + 1) * WU * A_;
            #pragma unroll
            for (int j = 0; j < WU; j++) {
                kn[j] = kp[o + (size_t)j * A_];
                vn[j] = vp[o + (size_t)j * A_];
                sn[j] = sp[o + (size_t)j * A_];
            }
        }
        const size_t yo = (size_t)g * WU * A_;
        #pragma unroll
        for (int j = 0; j < WU; j++) {
            const float kt = ka[j];
            const float vt = va[j];

            float ww = u + kt;
            float p  = fmaxf(pp, ww);
            float e1 = __expf(pp - p);
            float e2 = __expf(ww - p);
            const float y = (e1 * aa + e2 * vt) / (e1 * bb + e2);
            yp[yo + (size_t)j * A_] = __float2half(sa[j] * y);

            ww = pp + w;
            p  = fmaxf(ww, kt);
            e1 = __expf(ww - p);
            e2 = __expf(kt - p);
            aa = e1 * aa + e2 * vt;
            bb = e1 * bb + e2;
            pp = p;
        }
        #pragma unroll
        for (int j = 0; j < WU; j++) { ka[j] = kn[j]; va[j] = vn[j]; sa[j] = sn[j]; }
    }
    state_out[si + 0] = aa;
    state_out[si + 1] = bb;
    state_out[si + 2] = pp;
}

// ---------------- host launcher ----------------
extern "C" void kernel_launch(void* const* d_in, const int* in_sizes, int n_in,
                              void* d_out, int out_size)
{
    const float* x         = (const float*)d_in[0];
    const float* tm_shift  = (const float*)d_in[1];
    const float* wkv_state = (const float*)d_in[2];
    const float* cm_shift  = (const float*)d_in[3];
    const float* ln1_g     = (const float*)d_in[4];
    const float* ln1_b     = (const float*)d_in[5];
    const float* ln2_g     = (const float*)d_in[6];
    const float* ln2_b     = (const float*)d_in[7];
    const float* time_decay= (const float*)d_in[8];
    const float* time_first= (const float*)d_in[9];
    const float* att_mix_k = (const float*)d_in[10];
    const float* att_mix_v = (const float*)d_in[11];
    const float* att_mix_r = (const float*)d_in[12];
    const float* Wk        = (const float*)d_in[13];
    const float* Wv        = (const float*)d_in[14];
    const float* Wr        = (const float*)d_in[15];
    const float* Wo        = (const float*)d_in[16];
    const float* ffn_mix_k = (const float*)d_in[17];
    const float* ffn_mix_r = (const float*)d_in[18];
    const float* Wk_f      = (const float*)d_in[19];
    const float* Wr_f      = (const float*)d_in[20];
    const float* Wv_f      = (const float*)d_in[21];

    float* out     = (float*)d_out;
    float* out_x   = out;
    float* out_wkv = out + BTC;
    float* out_tm  = out_wkv + (size_t)B_ * C_ * 3;
    float* out_cm  = out_tm + (size_t)B_ * C_;

    float *kb, *vb, *srb, *x1, *rb;
    __half *ah, *ah2, *ah3, *kfb, *wb;
    cudaGetSymbolAddress((void**)&kb,  g_k);
    cudaGetSymbolAddress((void**)&vb,  g_v);
    cudaGetSymbolAddress((void**)&srb, g_sr);
    cudaGetSymbolAddress((void**)&x1,  g_x1);
    cudaGetSymbolAddress((void**)&rb,  g_r);
    cudaGetSymbolAddress((void**)&ah,  g_ah);
    cudaGetSymbolAddress((void**)&ah2, g_ah2);
    cudaGetSymbolAddress((void**)&ah3, g_ah3);
    cudaGetSymbolAddress((void**)&kfb, g_kf);
    cudaGetSymbolAddress((void**)&wb,  g_w);

    cudaFuncSetAttribute(gemm_h<0>, cudaFuncAttributeMaxDynamicSharedMemorySize, GEMM_SMEM);
    cudaFuncSetAttribute(gemm_h<1>, cudaFuncAttributeMaxDynamicSharedMemorySize, GEMM_SMEM);
    cudaFuncSetAttribute(gemm_h<2>, cudaFuncAttributeMaxDynamicSharedMemorySize, GEMM_SMEM);
    cudaFuncSetAttribute(gemm_h<3>, cudaFuncAttributeMaxDynamicSharedMemorySize, GEMM_SMEM);
    cudaFuncSetAttribute(gemm_h<4>, cudaFuncAttributeMaxDynamicSharedMemorySize, GEMM_SMEM);

    const int wCC = (int)((long)A_ * C_ / 4 / 256);      // 4096
    const int wFC = (int)((long)FF_ * C_ / 4 / 256);     // 16384
    const dim3 gA(A_ / BN,  M_ / BM);                    // (16, 128)
    const dim3 gC(C_ / BN,  M_ / BM);                    // (16, 128)
    const dim3 gF(FF_ / BN, M_ / BM);                    // (64, 128)

    // --- attention half ---
    ln_mix_kernel<3><<<M_, 256>>>(x, tm_shift, ln1_g, ln1_b,
                                  att_mix_k, att_mix_v, att_mix_r,
                                  ah, ah2, ah3, out_tm);

    convh_kernel<<<wCC, 256>>>(Wk, wb);
    gemm_h<0><<<gA, 256, GEMM_SMEM>>>(C_, A_, ah, wb, nullptr, nullptr, kb, nullptr);

    convh_kernel<<<wCC, 256>>>(Wv, wb);
    gemm_h<0><<<gA, 256, GEMM_SMEM>>>(C_, A_, ah2, wb, nullptr, nullptr, vb, nullptr);

    convh_kernel<<<wCC, 256>>>(Wr, wb);
    gemm_h<1><<<gA, 256, GEMM_SMEM>>>(C_, A_, ah3, wb, nullptr, nullptr, srb, nullptr);

    // wkv scan: writes ah = fp16(sr * y) directly
    wkv_kernel<<<(B_ * A_ + 63) / 64, 64>>>(time_decay, time_first,
                                            kb, vb, srb, wkv_state, ah, out_wkv);

    convh_kernel<<<wCC, 256>>>(Wo, wb);
    gemm_h<3><<<gC, 256, GEMM_SMEM>>>(A_, C_, ah, wb, x, nullptr, x1, nullptr);

    // --- FFN half ---
    ln_mix_kernel<2><<<M_, 256>>>(x1, cm_shift, ln2_g, ln2_b,
                                  ffn_mix_k, ffn_mix_r, nullptr,
                                  ah, ah2, nullptr, out_cm);

    convh_kernel<<<wFC, 256>>>(Wk_f, wb);
    gemm_h<2><<<gF, 256, GEMM_SMEM>>>(C_, FF_, ah, wb, nullptr, nullptr, nullptr, kfb);

    convh_kernel<<<wCC, 256>>>(Wr_f, wb);
    gemm_h<1><<<gC, 256, GEMM_SMEM>>>(C_, C_, ah2, wb, nullptr, nullptr, rb, nullptr);

    convh_kernel<<<wFC, 256>>>(Wv_f, wb);
    // fused final: out = x1 + rb * (kf @ Wv_f^T)
    gemm_h<4><<<gC, 256, GEMM_SMEM>>>(FF_, C_, kfb, wb, x1, rb, out_x, nullptr);
}